// round 13
// baseline (speedup 1.0000x reference)
#include <cuda_runtime.h>
#include <cuda_fp16.h>
#include <math.h>
#include <stdint.h>

// Problem constants
#define BW    1024          // windows (batch)
#define NTOK  64            // tokens per window (8x8)
#define CDIM  512           // channels
#define HEADS 16
#define HD    32            // head dim
#define BNC   (BW*NTOK*CDIM)

// Half scratch slots:
// slot 0: dwq -> later attention output
// slot 1: dwk   slot 2: dwv
// slot 3: q (pre-scaled)   slot 4: k     slot 5: v
__device__ __half g_scrh[6][BNC];
// fp16-rounded weights: 0=pwq (pre-scaled by 1/sqrt(32)), 1=pwk, 2=pwv, 3=proj
__device__ __half g_wh[4][CDIM*CDIM];
// precomputed pos+mask (fp32): [b][n][m]
__device__ float g_pm[BW * NTOK * NTOK];

#define ATTN_SCALE 0.17677669529663687f   // 1/sqrt(32)

// ---------------------------------------------------------------------------
// Weight prep
// ---------------------------------------------------------------------------
__global__ void prep_w(const float* __restrict__ w0, const float* __restrict__ w1,
                       const float* __restrict__ w2, const float* __restrict__ w3)
{
    int idx = blockIdx.x * 256 + threadIdx.x;
    int w = idx >> 18, j = idx & 262143;
    const float* s = (w == 0) ? w0 : (w == 1) ? w1 : (w == 2) ? w2 : w3;
    float v = s[j];
    if (w == 0) v *= ATTN_SCALE;
    g_wh[w][j] = __float2half_rn(v);
}

// pm[b][n][m] = mask[b][n][m] + pos[n][m]
__global__ void prep_pm(const float* __restrict__ mask, const float* __restrict__ pos)
{
    const int idx4 = (blockIdx.x * 256 + threadIdx.x) * 4;   // 4 M floats total
    const int rem = idx4 & 4095;
    float4 mv = *(const float4*)(mask + idx4);
    float4 pv = *(const float4*)(pos + rem);
    float4 o;
    o.x = mv.x + pv.x; o.y = mv.y + pv.y;
    o.z = mv.z + pv.z; o.w = mv.w + pv.w;
    *(float4*)(g_pm + idx4) = o;
}

__device__ __forceinline__ uint32_t pack_h2(float lo, float hi)
{
    __half2 h = __floats2half2_rn(lo, hi);
    return *(uint32_t*)&h;
}

// ---------------------------------------------------------------------------
// Kernel 1: fused depthwise 3x3 (+bias, ReLU) — R8 version (measured best).
// ---------------------------------------------------------------------------
__global__ void dw3_kernel(const float* __restrict__ x,
                           const float* __restrict__ wq, const float* __restrict__ bq,
                           const float* __restrict__ wk, const float* __restrict__ bk,
                           const float* __restrict__ wv, const float* __restrict__ bv)
{
    const int b   = blockIdx.y;
    const int c0  = blockIdx.x * 128;
    const int tid = threadIdx.x;            // 256 threads

    __shared__ float sx[64][128];
    const float* xb = x + (size_t)b * NTOK * CDIM;

    #pragma unroll
    for (int i = tid; i < 64 * 128; i += 256) {
        int n = i >> 7, c = i & 127;
        sx[n][c] = xb[n * CDIM + c0 + c];
    }
    __syncthreads();

    const int cl   = tid & 127;
    const int c    = c0 + cl;
    const int half = tid >> 7;

    float wqr[9], wkr[9], wvr[9];
    #pragma unroll
    for (int j = 0; j < 9; ++j) {
        wqr[j] = wq[c * 9 + j];
        wkr[j] = wk[c * 9 + j];
        wvr[j] = wv[c * 9 + j];
    }
    const float bqr = bq[c], bkr = bk[c], bvr = bv[c];

    __half* oq = g_scrh[0] + (size_t)b * NTOK * CDIM;
    __half* ok = g_scrh[1] + (size_t)b * NTOK * CDIM;
    __half* ov = g_scrh[2] + (size_t)b * NTOK * CDIM;

    #pragma unroll 4
    for (int nn = 0; nn < 32; ++nn) {
        int n = half * 32 + nn;
        int l = n >> 3, w = n & 7;
        float aq = bqr, ak = bkr, av = bvr;
        #pragma unroll
        for (int dl = -1; dl <= 1; ++dl) {
            #pragma unroll
            for (int dw = -1; dw <= 1; ++dw) {
                int ll = l + dl, ww = w + dw;
                if (ll < 0 || ll > 7 || ww < 0 || ww > 7) continue;
                float xv = sx[ll * 8 + ww][cl];
                int j = (dl + 1) * 3 + (dw + 1);
                aq += xv * wqr[j];
                ak += xv * wkr[j];
                av += xv * wvr[j];
            }
        }
        int idx = n * CDIM + c;
        oq[idx] = __float2half_rn(fmaxf(aq, 0.0f));
        ok[idx] = __float2half_rn(fmaxf(ak, 0.0f));
        ov[idx] = __float2half_rn(fmaxf(av, 0.0f));
    }
}

// ---------------------------------------------------------------------------
// mma.sync / ldmatrix helpers
// ---------------------------------------------------------------------------
__device__ __forceinline__ void mma_f16(float* d, uint32_t a0, uint32_t a1,
                                        uint32_t a2, uint32_t a3,
                                        uint32_t b0, uint32_t b1)
{
    asm volatile(
        "mma.sync.aligned.m16n8k16.row.col.f32.f16.f16.f32 "
        "{%0,%1,%2,%3}, {%4,%5,%6,%7}, {%8,%9}, {%0,%1,%2,%3};"
        : "+f"(d[0]), "+f"(d[1]), "+f"(d[2]), "+f"(d[3])
        : "r"(a0), "r"(a1), "r"(a2), "r"(a3), "r"(b0), "r"(b1));
}

__device__ __forceinline__ void ldsm4(uint32_t& r0, uint32_t& r1,
                                      uint32_t& r2, uint32_t& r3, uint32_t addr)
{
    asm volatile("ldmatrix.sync.aligned.m8n8.x4.shared.b16 {%0,%1,%2,%3}, [%4];"
                 : "=r"(r0), "=r"(r1), "=r"(r2), "=r"(r3) : "r"(addr));
}

__device__ __forceinline__ void ldsm4t(uint32_t& r0, uint32_t& r1,
                                       uint32_t& r2, uint32_t& r3, uint32_t addr)
{
    asm volatile("ldmatrix.sync.aligned.m8n8.x4.trans.shared.b16 {%0,%1,%2,%3}, [%4];"
                 : "=r"(r0), "=r"(r1), "=r"(r2), "=r"(r3) : "r"(addr));
}

__device__ __forceinline__ void cp16(uint32_t dst, const void* src)
{
    asm volatile("cp.async.cg.shared.global [%0], [%1], 16;"
                 :: "r"(dst), "l"(src) : "memory");
}

// ---------------------------------------------------------------------------
// fp16 GEMM body: C[65536,512] = A @ W^T + bias
// CTA 128x128, 256 threads = 8 warps (2 m-halves x 4 n-quarters),
// warp tile 64x32 -> acc 64 regs -> 2 CTAs/SM = 16 warps (occupancy lever).
// K-chunk 32 = two k16 slabs per stage, 3-stage cp.async ring.
// Smem layout / fill pattern / fragment addressing identical to the
// measured-good R12 scheme (PADH=12, bank-verified).
// ---------------------------------------------------------------------------
#define PADH 12
#define SLAB 1536                      // u32 per k16 slab per matrix
#define STGU (2 * SLAB)                // u32 per k32 stage per matrix
#define GSMEM_BYTES (3 * STGU * 4 * 2) // 73728

__device__ __forceinline__ void gemm_body_h(const __half* __restrict__ A,
                                            const __half* __restrict__ W,
                                            const float* __restrict__ bias,
                                            float bscale,
                                            __half* __restrict__ Ch,
                                            float* __restrict__ Cf)
{
    extern __shared__ uint32_t dsm[];
    uint32_t* smA = dsm;               // 3 * STGU
    uint32_t* smB = dsm + 3 * STGU;

    const int tid  = threadIdx.x;      // 256 threads
    const int wid  = tid >> 5;
    const int lane = tid & 31;
    const int wm   = wid >> 2;         // 0..1 : 64-row half
    const int wn   = wid & 3;          // 0..3 : 32-col quarter
    const int m0 = blockIdx.y * 128;
    const int n0 = blockIdx.x * 128;

    const int lrow = tid >> 1;         // 0..127 (one row per thread-pair)
    const int seg  = tid & 1;          // 8-half segment within k16

    const int qrow = lane >> 2;
    const int qcol = lane & 3;

    const uint32_t sAb = (uint32_t)__cvta_generic_to_shared(smA);
    const uint32_t sBb = (uint32_t)__cvta_generic_to_shared(smB);

    float acc[4][4][4];
    #pragma unroll
    for (int i = 0; i < 4; ++i)
        #pragma unroll
        for (int j = 0; j < 4; ++j)
            #pragma unroll
            for (int r = 0; r < 4; ++r) acc[i][j][r] = 0.0f;

    const __half* Ap = A + (size_t)(m0 + lrow) * 512 + seg * 8;
    const __half* Bp = W + (size_t)(n0 + lrow) * 512 + seg * 8;

    // prologue: stages 0,1 (k32 chunks 0,1)
    #pragma unroll
    for (int st = 0; st < 2; ++st) {
        #pragma unroll
        for (int h = 0; h < 2; ++h) {
            const uint32_t off = (uint32_t)((st * STGU + h * SLAB +
                                lrow * PADH + seg * 4) * 4);
            cp16(sAb + off, Ap + st * 32 + h * 16);
            cp16(sBb + off, Bp + st * 32 + h * 16);
        }
        asm volatile("cp.async.commit_group;" ::: "memory");
    }

    int s = 0, p = 2;
    #pragma unroll 1
    for (int ch = 0; ch < 16; ++ch) {
        asm volatile("cp.async.wait_group 1;" ::: "memory");
        __syncthreads();

        if (ch < 14) {
            const int kb = (ch + 2) * 32;
            #pragma unroll
            for (int h = 0; h < 2; ++h) {
                const uint32_t off = (uint32_t)((p * STGU + h * SLAB +
                                    lrow * PADH + seg * 4) * 4);
                cp16(sAb + off, Ap + kb + h * 16);
                cp16(sBb + off, Bp + kb + h * 16);
            }
        }
        asm volatile("cp.async.commit_group;" ::: "memory");

        #pragma unroll
        for (int h = 0; h < 2; ++h) {
            const uint32_t* Ab = smA + s * STGU + h * SLAB;
            const uint32_t* Bb = smB + s * STGU + h * SLAB;

            uint32_t a[4][4];
            #pragma unroll
            for (int mi = 0; mi < 4; ++mi) {
                const int mr = wm * 64 + mi * 16 + qrow;
                a[mi][0] = Ab[mr * PADH + qcol];
                a[mi][1] = Ab[(mr + 8) * PADH + qcol];
                a[mi][2] = Ab[mr * PADH + qcol + 4];
                a[mi][3] = Ab[(mr + 8) * PADH + qcol + 4];
            }
            uint32_t bfr[4][2];
            #pragma unroll
            for (int ni = 0; ni < 4; ++ni) {
                const int nc = wn * 32 + ni * 8 + qrow;
                bfr[ni][0] = Bb[nc * PADH + qcol];
                bfr[ni][1] = Bb[nc * PADH + qcol + 4];
            }
            #pragma unroll
            for (int mi = 0; mi < 4; ++mi)
                #pragma unroll
                for (int ni = 0; ni < 4; ++ni)
                    mma_f16(acc[mi][ni], a[mi][0], a[mi][1], a[mi][2], a[mi][3],
                            bfr[ni][0], bfr[ni][1]);
        }

        s = (s == 2) ? 0 : s + 1;
        p = (p == 2) ? 0 : p + 1;
    }

    // Epilogue: bias (optionally scaled), half2 or float2 stores
    #pragma unroll
    for (int ni = 0; ni < 4; ++ni) {
        const int n = n0 + wn * 32 + ni * 8 + (qcol << 1);
        const float bx = bias[n] * bscale;
        const float by = bias[n + 1] * bscale;
        #pragma unroll
        for (int mi = 0; mi < 4; ++mi) {
            const int m = m0 + wm * 64 + mi * 16 + qrow;
            const float f0 = acc[mi][ni][0] + bx, f1 = acc[mi][ni][1] + by;
            const float f2 = acc[mi][ni][2] + bx, f3 = acc[mi][ni][3] + by;
            if (Ch) {
                *(uint32_t*)(Ch + (size_t)m * 512 + n)       = pack_h2(f0, f1);
                *(uint32_t*)(Ch + (size_t)(m + 8) * 512 + n) = pack_h2(f2, f3);
            } else {
                *(float2*)(Cf + (size_t)m * 512 + n)       = make_float2(f0, f1);
                *(float2*)(Cf + (size_t)(m + 8) * 512 + n) = make_float2(f2, f3);
            }
        }
    }
}

// QKV: grid.z selects slot (0,1,2) -> writes slots (3,4,5).
__global__ void __launch_bounds__(256, 2)
gemm_qkv(const float* __restrict__ bq, const float* __restrict__ bk,
         const float* __restrict__ bv)
{
    const int z = blockIdx.z;
    const float* bias = (z == 0) ? bq : (z == 1) ? bk : bv;
    const float bscale = (z == 0) ? ATTN_SCALE : 1.0f;
    gemm_body_h(g_scrh[z], g_wh[z], bias, bscale, g_scrh[3 + z], nullptr);
}

__global__ void __launch_bounds__(256, 2)
gemm_proj(const float* __restrict__ bias, float* __restrict__ C)
{
    gemm_body_h(g_scrh[0], g_wh[3], bias, 1.0f, nullptr, C);
}

// ---------------------------------------------------------------------------
// Kernel 3: fp16 tensor-core attention (R12 version — unchanged).
// ---------------------------------------------------------------------------
__global__ void __launch_bounds__(128)
attn_h()
{
    const int bh = blockIdx.x;
    const int b = bh >> 4;
    const int h = bh & 15;
    const int tid  = threadIdx.x;
    const int wid  = tid >> 5;
    const int lane = tid & 31;
    const int qrow = lane >> 2;
    const int qcol = lane & 3;
    const int mat  = lane >> 3;
    const int rr   = lane & 7;

    __shared__ uint32_t Qs[64 * 20];   // [token][16 half2 + pad], pitch 80B
    __shared__ uint32_t Ks[64 * 20];
    __shared__ uint32_t Vs[64 * 20];

    const __half* Q = g_scrh[3];
    const __half* K = g_scrh[4];
    const __half* V = g_scrh[5];
    const size_t base = (size_t)b * 64 * 512 + h * 32;

    #pragma unroll
    for (int i = tid; i < 256; i += 128) {
        const int t = i >> 2, g = i & 3;
        const size_t gofs = base + (size_t)t * 512 + g * 8;
        *(uint4*)((char*)Qs + t * 80 + g * 16) = *(const uint4*)(Q + gofs);
        *(uint4*)((char*)Ks + t * 80 + g * 16) = *(const uint4*)(K + gofs);
        *(uint4*)((char*)Vs + t * 80 + g * 16) = *(const uint4*)(V + gofs);
    }
    __syncthreads();

    const uint32_t uQ = (uint32_t)__cvta_generic_to_shared(Qs);
    const uint32_t uK = (uint32_t)__cvta_generic_to_shared(Ks);
    const uint32_t uV = (uint32_t)__cvta_generic_to_shared(Vs);

    // S = Q K^T  (warp rows m0..m0+15; q pre-scaled)
    const int m0 = wid * 16;
    const uint32_t aQ0 = (uint32_t)((m0 + ((mat & 1) << 3) + rr) * 80 + ((mat >> 1) << 4));
    const uint32_t bK0 = (uint32_t)((((mat >> 1) << 3) + rr) * 80 + ((mat & 1) << 4));
    const uint32_t bV0 = (uint32_t)((((mat & 1) << 3) + rr) * 80 + ((mat >> 1) << 4));

    float acc[8][4];
    #pragma unroll
    for (int nt = 0; nt < 8; ++nt)
        #pragma unroll
        for (int r = 0; r < 4; ++r) acc[nt][r] = 0.0f;

    #pragma unroll
    for (int kt = 0; kt < 2; ++kt) {
        uint32_t a0, a1, a2, a3;
        ldsm4(a0, a1, a2, a3, uQ + aQ0 + kt * 32);
        #pragma unroll
        for (int pi = 0; pi < 4; ++pi) {
            uint32_t b0, b1, b2, b3;
            ldsm4(b0, b1, b2, b3, uK + bK0 + pi * 1280 + kt * 32);
            mma_f16(acc[2 * pi],     a0, a1, a2, a3, b0, b1);
            mma_f16(acc[2 * pi + 1], a0, a1, a2, a3, b2, b3);
        }
    }

    // + (pos+mask) precomputed; fragment softmax (quad shfl reductions)
    const int r0 = m0 + qrow, r1 = r0 + 8;
    const int cb = qcol * 2;
    const float* pmb = g_pm + (size_t)b * 4096;
    float mx0 = -1e30f, mx1 = -1e30f;
    #pragma unroll
    for (int nt = 0; nt < 8; ++nt) {
        const int col = nt * 8 + cb;
        const float2 p0 = *(const float2*)(pmb + r0 * 64 + col);
        const float2 p1 = *(const float2*)(pmb + r1 * 64 + col);
        acc[nt][0] += p0.x;
        acc[nt][1] += p0.y;
        acc[nt][2] += p1.x;
        acc[nt][3] += p1.y;
        mx0 = fmaxf(mx0, fmaxf(acc[nt][0], acc[nt][1]));
        mx1 = fmaxf(mx1, fmaxf(acc[nt][2], acc[nt][3]));
    }
    mx0 = fmaxf(mx0, __shfl_xor_sync(0xffffffffu, mx0, 1));
    mx0 = fmaxf(mx0, __shfl_xor_sync(0xffffffffu, mx0, 2));
    mx1 = fmaxf(mx1, __shfl_xor_sync(0xffffffffu, mx1, 1));
    mx1 = fmaxf(mx1, __shfl_xor_sync(0xffffffffu, mx1, 2));

    float s0 = 0.0f, s1 = 0.0f;
    #pragma unroll
    for (int nt = 0; nt < 8; ++nt) {
        acc[nt][0] = __expf(acc[nt][0] - mx0);
        acc[nt][1] = __expf(acc[nt][1] - mx0);
        acc[nt][2] = __expf(acc[nt][2] - mx1);
        acc[nt][3] = __expf(acc[nt][3] - mx1);
        s0 += acc[nt][0] + acc[nt][1];
        s1 += acc[nt][2] + acc[nt][3];
    }
    s0 += __shfl_xor_sync(0xffffffffu, s0, 1);
    s0 += __shfl_xor_sync(0xffffffffu, s0, 2);
    s1 += __shfl_xor_sync(0xffffffffu, s1, 1);
    s1 += __shfl_xor_sync(0xffffffffu, s1, 2);
    const float inv0 = 1.0f / s0;
    const float inv1 = 1.0f / s1;

    // O = P V : P a-frags packed directly from the S C-frags (no smem).
    float oacc[4][4];
    #pragma unroll
    for (int nt = 0; nt < 4; ++nt)
        #pragma unroll
        for (int r = 0; r < 4; ++r) oacc[nt][r] = 0.0f;

    #pragma unroll
    for (int kt = 0; kt < 4; ++kt) {
        const uint32_t a0 = pack_h2(acc[2 * kt][0],     acc[2 * kt][1]);
        const uint32_t a1 = pack_h2(acc[2 * kt][2],     acc[2 * kt][3]);
        const uint32_t a2 = pack_h2(acc[2 * kt + 1][0], acc[2 * kt + 1][1]);
        const uint32_t a3 = pack_h2(acc[2 * kt + 1][2], acc[2 * kt + 1][3]);
        #pragma unroll
        for (int np = 0; np < 2; ++np) {
            uint32_t b0, b1, b2, b3;
            ldsm4t(b0, b1, b2, b3, uV + bV0 + kt * 16 * 80 + np * 32);
            mma_f16(oacc[2 * np],     a0, a1, a2, a3, b0, b1);
            mma_f16(oacc[2 * np + 1], a0, a1, a2, a3, b2, b3);
        }
    }

    // normalize, pack, store to slot 0 at [token][h*32+dim]
    __half* O = g_scrh[0] + base;
    #pragma unroll
    for (int nt = 0; nt < 4; ++nt) {
        const int col = nt * 8 + cb;
        *(uint32_t*)(O + (size_t)r0 * 512 + col) =
            pack_h2(oacc[nt][0] * inv0, oacc[nt][1] * inv0);
        *(uint32_t*)(O + (size_t)r1 * 512 + col) =
            pack_h2(oacc[nt][2] * inv1, oacc[nt][3] * inv1);
    }
}

// ---------------------------------------------------------------------------
// Launch
// ---------------------------------------------------------------------------
extern "C" void kernel_launch(void* const* d_in, const int* in_sizes, int n_in,
                              void* d_out, int out_size)
{
    const float* x      = (const float*)d_in[0];
    const float* mask   = (const float*)d_in[1];
    const float* dwq_w  = (const float*)d_in[2];
    const float* dwq_b  = (const float*)d_in[3];
    const float* pwq_w  = (const float*)d_in[4];
    const float* pwq_b  = (const float*)d_in[5];
    const float* dwk_w  = (const float*)d_in[6];
    const float* dwk_b  = (const float*)d_in[7];
    const float* pwk_w  = (const float*)d_in[8];
    const float* pwk_b  = (const float*)d_in[9];
    const float* dwv_w  = (const float*)d_in[10];
    const float* dwv_b  = (const float*)d_in[11];
    const float* pwv_w  = (const float*)d_in[12];
    const float* pwv_b  = (const float*)d_in[13];
    const float* pos    = (const float*)d_in[14];
    const float* proj_w = (const float*)d_in[15];
    const float* proj_b = (const float*)d_in[16];

    cudaFuncSetAttribute(gemm_qkv, cudaFuncAttributeMaxDynamicSharedMemorySize, GSMEM_BYTES);
    cudaFuncSetAttribute(gemm_proj, cudaFuncAttributeMaxDynamicSharedMemorySize, GSMEM_BYTES);

    // 0. round weights to fp16 (w0 pre-scaled); precompute pos+mask
    prep_w<<<4096, 256>>>(pwq_w, pwk_w, pwv_w, proj_w);
    prep_pm<<<4096, 256>>>(mask, pos);

    // 1. depthwise 3x3 + ReLU -> slots 0,1,2 (fp16)
    dim3 gdw(4, BW);
    dw3_kernel<<<gdw, 256>>>(x, dwq_w, dwq_b, dwk_w, dwk_b, dwv_w, dwv_b);

    // 2. pointwise GEMMs (fp16 mma, 8-warp CTAs) -> slots 3,4,5
    dim3 gqkv(4, 512, 3);
    gemm_qkv<<<gqkv, 256, GSMEM_BYTES>>>(pwq_b, pwk_b, pwv_b);

    // 3. fp16 tensor-core attention -> slot 0
    attn_h<<<BW * HEADS, 128>>>();

    // 4. output projection -> d_out (f32)
    dim3 gg(4, 512);
    gemm_proj<<<gg, 256, GSMEM_BYTES>>>(proj_b, (float*)d_out);
}

// round 14
// speedup vs baseline: 1.0966x; 1.0966x over previous
#include <cuda_runtime.h>
#include <cuda_fp16.h>
#include <math.h>
#include <stdint.h>

// Problem constants
#define BW    1024          // windows (batch)
#define NTOK  64            // tokens per window (8x8)
#define CDIM  512           // channels
#define HEADS 16
#define HD    32            // head dim
#define BNC   (BW*NTOK*CDIM)

// Half scratch slots:
// slot 0: dwq -> later attention output
// slot 1: dwk   slot 2: dwv
// slot 3: q (pre-scaled)   slot 4: k     slot 5: v
__device__ __half g_scrh[6][BNC];
// fp16-rounded weights: 0=pwq (pre-scaled by 1/sqrt(32)), 1=pwk, 2=pwv, 3=proj
__device__ __half g_wh[4][CDIM*CDIM];
// precomputed pos+mask (fp32): [b][n][m]
__device__ float g_pm[BW * NTOK * NTOK];

#define ATTN_SCALE 0.17677669529663687f   // 1/sqrt(32)

// ---------------------------------------------------------------------------
// Weight prep
// ---------------------------------------------------------------------------
__global__ void prep_w(const float* __restrict__ w0, const float* __restrict__ w1,
                       const float* __restrict__ w2, const float* __restrict__ w3)
{
    int idx = blockIdx.x * 256 + threadIdx.x;
    int w = idx >> 18, j = idx & 262143;
    const float* s = (w == 0) ? w0 : (w == 1) ? w1 : (w == 2) ? w2 : w3;
    float v = s[j];
    if (w == 0) v *= ATTN_SCALE;
    g_wh[w][j] = __float2half_rn(v);
}

// pm[b][n][m] = mask[b][n][m] + pos[n][m]
__global__ void prep_pm(const float* __restrict__ mask, const float* __restrict__ pos)
{
    const int idx4 = (blockIdx.x * 256 + threadIdx.x) * 4;   // 4 M floats total
    const int rem = idx4 & 4095;
    float4 mv = *(const float4*)(mask + idx4);
    float4 pv = *(const float4*)(pos + rem);
    float4 o;
    o.x = mv.x + pv.x; o.y = mv.y + pv.y;
    o.z = mv.z + pv.z; o.w = mv.w + pv.w;
    *(float4*)(g_pm + idx4) = o;
}

__device__ __forceinline__ uint32_t pack_h2(float lo, float hi)
{
    __half2 h = __floats2half2_rn(lo, hi);
    return *(uint32_t*)&h;
}

// ---------------------------------------------------------------------------
// Kernel 1: fused depthwise 3x3 (+bias, ReLU) — R8 version (measured best).
// ---------------------------------------------------------------------------
__global__ void dw3_kernel(const float* __restrict__ x,
                           const float* __restrict__ wq, const float* __restrict__ bq,
                           const float* __restrict__ wk, const float* __restrict__ bk,
                           const float* __restrict__ wv, const float* __restrict__ bv)
{
    const int b   = blockIdx.y;
    const int c0  = blockIdx.x * 128;
    const int tid = threadIdx.x;            // 256 threads

    __shared__ float sx[64][128];
    const float* xb = x + (size_t)b * NTOK * CDIM;

    #pragma unroll
    for (int i = tid; i < 64 * 128; i += 256) {
        int n = i >> 7, c = i & 127;
        sx[n][c] = xb[n * CDIM + c0 + c];
    }
    __syncthreads();

    const int cl   = tid & 127;
    const int c    = c0 + cl;
    const int half = tid >> 7;

    float wqr[9], wkr[9], wvr[9];
    #pragma unroll
    for (int j = 0; j < 9; ++j) {
        wqr[j] = wq[c * 9 + j];
        wkr[j] = wk[c * 9 + j];
        wvr[j] = wv[c * 9 + j];
    }
    const float bqr = bq[c], bkr = bk[c], bvr = bv[c];

    __half* oq = g_scrh[0] + (size_t)b * NTOK * CDIM;
    __half* ok = g_scrh[1] + (size_t)b * NTOK * CDIM;
    __half* ov = g_scrh[2] + (size_t)b * NTOK * CDIM;

    #pragma unroll 4
    for (int nn = 0; nn < 32; ++nn) {
        int n = half * 32 + nn;
        int l = n >> 3, w = n & 7;
        float aq = bqr, ak = bkr, av = bvr;
        #pragma unroll
        for (int dl = -1; dl <= 1; ++dl) {
            #pragma unroll
            for (int dw = -1; dw <= 1; ++dw) {
                int ll = l + dl, ww = w + dw;
                if (ll < 0 || ll > 7 || ww < 0 || ww > 7) continue;
                float xv = sx[ll * 8 + ww][cl];
                int j = (dl + 1) * 3 + (dw + 1);
                aq += xv * wqr[j];
                ak += xv * wkr[j];
                av += xv * wvr[j];
            }
        }
        int idx = n * CDIM + c;
        oq[idx] = __float2half_rn(fmaxf(aq, 0.0f));
        ok[idx] = __float2half_rn(fmaxf(ak, 0.0f));
        ov[idx] = __float2half_rn(fmaxf(av, 0.0f));
    }
}

// ---------------------------------------------------------------------------
// mma.sync / ldmatrix helpers
// ---------------------------------------------------------------------------
__device__ __forceinline__ void mma_f16(float* d, uint32_t a0, uint32_t a1,
                                        uint32_t a2, uint32_t a3,
                                        uint32_t b0, uint32_t b1)
{
    asm volatile(
        "mma.sync.aligned.m16n8k16.row.col.f32.f16.f16.f32 "
        "{%0,%1,%2,%3}, {%4,%5,%6,%7}, {%8,%9}, {%0,%1,%2,%3};"
        : "+f"(d[0]), "+f"(d[1]), "+f"(d[2]), "+f"(d[3])
        : "r"(a0), "r"(a1), "r"(a2), "r"(a3), "r"(b0), "r"(b1));
}

__device__ __forceinline__ void ldsm4(uint32_t& r0, uint32_t& r1,
                                      uint32_t& r2, uint32_t& r3, uint32_t addr)
{
    asm volatile("ldmatrix.sync.aligned.m8n8.x4.shared.b16 {%0,%1,%2,%3}, [%4];"
                 : "=r"(r0), "=r"(r1), "=r"(r2), "=r"(r3) : "r"(addr));
}

__device__ __forceinline__ void ldsm4t(uint32_t& r0, uint32_t& r1,
                                       uint32_t& r2, uint32_t& r3, uint32_t addr)
{
    asm volatile("ldmatrix.sync.aligned.m8n8.x4.trans.shared.b16 {%0,%1,%2,%3}, [%4];"
                 : "=r"(r0), "=r"(r1), "=r"(r2), "=r"(r3) : "r"(addr));
}

__device__ __forceinline__ void cp16(uint32_t dst, const void* src)
{
    asm volatile("cp.async.cg.shared.global [%0], [%1], 16;"
                 :: "r"(dst), "l"(src) : "memory");
}

// ---------------------------------------------------------------------------
// fp16 GEMM body (R8 version, byte-exact — measured best): C = A @ W^T + bias
// CTA 128x128, 128 threads = 4 warps (2x2), warp tile 64x64, m16n8k16.
// K-chunk 16, 3-stage cp.async ring, one sync per chunk.
// Smem rows = 8 half2 data + pad -> pitch 12 half2 (bank-conflict-free).
// ---------------------------------------------------------------------------
#define PADH 12
#define HST  (128 * PADH)                 // half2 (=u32) per stage per matrix

__device__ __forceinline__ void gemm_body_h(const __half* __restrict__ A,
                                            const __half* __restrict__ W,
                                            const float* __restrict__ bias,
                                            float bscale,
                                            __half* __restrict__ Ch,
                                            float* __restrict__ Cf)
{
    __shared__ uint32_t smA[3 * HST];
    __shared__ uint32_t smB[3 * HST];

    const int tid  = threadIdx.x;           // 128 threads
    const int wid  = tid >> 5;
    const int lane = tid & 31;
    const int wm   = wid & 1;
    const int wn   = wid >> 1;
    const int m0 = blockIdx.y * 128;
    const int n0 = blockIdx.x * 128;

    const int lrow = tid >> 1;              // 0..63
    const int seg  = tid & 1;               // 8-half segment within k16

    const int qrow = lane >> 2;
    const int qcol = lane & 3;

    const uint32_t sAb = (uint32_t)__cvta_generic_to_shared(smA);
    const uint32_t sBb = (uint32_t)__cvta_generic_to_shared(smB);

    float acc[4][8][4];
    #pragma unroll
    for (int i = 0; i < 4; ++i)
        #pragma unroll
        for (int j = 0; j < 8; ++j)
            #pragma unroll
            for (int r = 0; r < 4; ++r) acc[i][j][r] = 0.0f;

    const __half* Ap = A + (size_t)(m0 + lrow) * 512 + seg * 8;
    const __half* Bp = W + (size_t)(n0 + lrow) * 512 + seg * 8;

    // prologue: stages 0,1
    #pragma unroll
    for (int st = 0; st < 2; ++st) {
        #pragma unroll
        for (int r = 0; r < 2; ++r) {
            uint32_t off = (uint32_t)(((st * 128 + lrow + r * 64) * PADH + seg * 4) * 4);
            cp16(sAb + off, Ap + (size_t)(r * 64) * 512 + st * 16);
            cp16(sBb + off, Bp + (size_t)(r * 64) * 512 + st * 16);
        }
        asm volatile("cp.async.commit_group;" ::: "memory");
    }

    int s = 0, p = 2;
    #pragma unroll 1
    for (int ch = 0; ch < 32; ++ch) {
        asm volatile("cp.async.wait_group 1;" ::: "memory");
        __syncthreads();

        if (ch < 30) {
            const int kb = (ch + 2) * 16;
            #pragma unroll
            for (int r = 0; r < 2; ++r) {
                uint32_t off = (uint32_t)(((p * 128 + lrow + r * 64) * PADH + seg * 4) * 4);
                cp16(sAb + off, Ap + (size_t)(r * 64) * 512 + kb);
                cp16(sBb + off, Bp + (size_t)(r * 64) * 512 + kb);
            }
        }
        asm volatile("cp.async.commit_group;" ::: "memory");

        const uint32_t* Ab = smA + s * HST;
        const uint32_t* Bb = smB + s * HST;

        uint32_t a[4][4];
        #pragma unroll
        for (int mi = 0; mi < 4; ++mi) {
            const int mr = wm * 64 + mi * 16 + qrow;
            a[mi][0] = Ab[mr * PADH + qcol];
            a[mi][1] = Ab[(mr + 8) * PADH + qcol];
            a[mi][2] = Ab[mr * PADH + qcol + 4];
            a[mi][3] = Ab[(mr + 8) * PADH + qcol + 4];
        }
        uint32_t bfr[8][2];
        #pragma unroll
        for (int ni = 0; ni < 8; ++ni) {
            const int nc = wn * 64 + ni * 8 + qrow;
            bfr[ni][0] = Bb[nc * PADH + qcol];
            bfr[ni][1] = Bb[nc * PADH + qcol + 4];
        }
        #pragma unroll
        for (int mi = 0; mi < 4; ++mi)
            #pragma unroll
            for (int ni = 0; ni < 8; ++ni)
                mma_f16(acc[mi][ni], a[mi][0], a[mi][1], a[mi][2], a[mi][3],
                        bfr[ni][0], bfr[ni][1]);

        s = (s == 2) ? 0 : s + 1;
        p = (p == 2) ? 0 : p + 1;
    }

    // Epilogue: bias (optionally scaled), half2 or float2 stores
    #pragma unroll
    for (int ni = 0; ni < 8; ++ni) {
        const int n = n0 + wn * 64 + ni * 8 + (qcol << 1);
        const float bx = bias[n] * bscale;
        const float by = bias[n + 1] * bscale;
        #pragma unroll
        for (int mi = 0; mi < 4; ++mi) {
            const int m = m0 + wm * 64 + mi * 16 + qrow;
            const float f0 = acc[mi][ni][0] + bx, f1 = acc[mi][ni][1] + by;
            const float f2 = acc[mi][ni][2] + bx, f3 = acc[mi][ni][3] + by;
            if (Ch) {
                *(uint32_t*)(Ch + (size_t)m * 512 + n)       = pack_h2(f0, f1);
                *(uint32_t*)(Ch + (size_t)(m + 8) * 512 + n) = pack_h2(f2, f3);
            } else {
                *(float2*)(Cf + (size_t)m * 512 + n)       = make_float2(f0, f1);
                *(float2*)(Cf + (size_t)(m + 8) * 512 + n) = make_float2(f2, f3);
            }
        }
    }
}

// QKV: grid.z selects slot (0,1,2) -> writes slots (3,4,5).
__global__ void __launch_bounds__(128, 3)
gemm_qkv(const float* __restrict__ bq, const float* __restrict__ bk,
         const float* __restrict__ bv)
{
    const int z = blockIdx.z;
    const float* bias = (z == 0) ? bq : (z == 1) ? bk : bv;
    const float bscale = (z == 0) ? ATTN_SCALE : 1.0f;
    gemm_body_h(g_scrh[z], g_wh[z], bias, bscale, g_scrh[3 + z], nullptr);
}

__global__ void __launch_bounds__(128, 3)
gemm_proj(const float* __restrict__ bias, float* __restrict__ C)
{
    gemm_body_h(g_scrh[0], g_wh[3], bias, 1.0f, nullptr, C);
}

// ---------------------------------------------------------------------------
// Kernel 3: fp16 tensor-core attention (R12 version — measured best, pm).
// ---------------------------------------------------------------------------
__global__ void __launch_bounds__(128)
attn_h()
{
    const int bh = blockIdx.x;
    const int b = bh >> 4;
    const int h = bh & 15;
    const int tid  = threadIdx.x;
    const int wid  = tid >> 5;
    const int lane = tid & 31;
    const int qrow = lane >> 2;
    const int qcol = lane & 3;
    const int mat  = lane >> 3;
    const int rr   = lane & 7;

    __shared__ uint32_t Qs[64 * 20];   // [token][16 half2 + pad], pitch 80B
    __shared__ uint32_t Ks[64 * 20];
    __shared__ uint32_t Vs[64 * 20];

    const __half* Q = g_scrh[3];
    const __half* K = g_scrh[4];
    const __half* V = g_scrh[5];
    const size_t base = (size_t)b * 64 * 512 + h * 32;

    #pragma unroll
    for (int i = tid; i < 256; i += 128) {
        const int t = i >> 2, g = i & 3;
        const size_t gofs = base + (size_t)t * 512 + g * 8;
        *(uint4*)((char*)Qs + t * 80 + g * 16) = *(const uint4*)(Q + gofs);
        *(uint4*)((char*)Ks + t * 80 + g * 16) = *(const uint4*)(K + gofs);
        *(uint4*)((char*)Vs + t * 80 + g * 16) = *(const uint4*)(V + gofs);
    }
    __syncthreads();

    const uint32_t uQ = (uint32_t)__cvta_generic_to_shared(Qs);
    const uint32_t uK = (uint32_t)__cvta_generic_to_shared(Ks);
    const uint32_t uV = (uint32_t)__cvta_generic_to_shared(Vs);

    // S = Q K^T  (warp rows m0..m0+15; q pre-scaled)
    const int m0 = wid * 16;
    const uint32_t aQ0 = (uint32_t)((m0 + ((mat & 1) << 3) + rr) * 80 + ((mat >> 1) << 4));
    const uint32_t bK0 = (uint32_t)((((mat >> 1) << 3) + rr) * 80 + ((mat & 1) << 4));
    const uint32_t bV0 = (uint32_t)((((mat & 1) << 3) + rr) * 80 + ((mat >> 1) << 4));

    float acc[8][4];
    #pragma unroll
    for (int nt = 0; nt < 8; ++nt)
        #pragma unroll
        for (int r = 0; r < 4; ++r) acc[nt][r] = 0.0f;

    #pragma unroll
    for (int kt = 0; kt < 2; ++kt) {
        uint32_t a0, a1, a2, a3;
        ldsm4(a0, a1, a2, a3, uQ + aQ0 + kt * 32);
        #pragma unroll
        for (int pi = 0; pi < 4; ++pi) {
            uint32_t b0, b1, b2, b3;
            ldsm4(b0, b1, b2, b3, uK + bK0 + pi * 1280 + kt * 32);
            mma_f16(acc[2 * pi],     a0, a1, a2, a3, b0, b1);
            mma_f16(acc[2 * pi + 1], a0, a1, a2, a3, b2, b3);
        }
    }

    // + (pos+mask) precomputed; fragment softmax (quad shfl reductions)
    const int r0 = m0 + qrow, r1 = r0 + 8;
    const int cb = qcol * 2;
    const float* pmb = g_pm + (size_t)b * 4096;
    float mx0 = -1e30f, mx1 = -1e30f;
    #pragma unroll
    for (int nt = 0; nt < 8; ++nt) {
        const int col = nt * 8 + cb;
        const float2 p0 = *(const float2*)(pmb + r0 * 64 + col);
        const float2 p1 = *(const float2*)(pmb + r1 * 64 + col);
        acc[nt][0] += p0.x;
        acc[nt][1] += p0.y;
        acc[nt][2] += p1.x;
        acc[nt][3] += p1.y;
        mx0 = fmaxf(mx0, fmaxf(acc[nt][0], acc[nt][1]));
        mx1 = fmaxf(mx1, fmaxf(acc[nt][2], acc[nt][3]));
    }
    mx0 = fmaxf(mx0, __shfl_xor_sync(0xffffffffu, mx0, 1));
    mx0 = fmaxf(mx0, __shfl_xor_sync(0xffffffffu, mx0, 2));
    mx1 = fmaxf(mx1, __shfl_xor_sync(0xffffffffu, mx1, 1));
    mx1 = fmaxf(mx1, __shfl_xor_sync(0xffffffffu, mx1, 2));

    float s0 = 0.0f, s1 = 0.0f;
    #pragma unroll
    for (int nt = 0; nt < 8; ++nt) {
        acc[nt][0] = __expf(acc[nt][0] - mx0);
        acc[nt][1] = __expf(acc[nt][1] - mx0);
        acc[nt][2] = __expf(acc[nt][2] - mx1);
        acc[nt][3] = __expf(acc[nt][3] - mx1);
        s0 += acc[nt][0] + acc[nt][1];
        s1 += acc[nt][2] + acc[nt][3];
    }
    s0 += __shfl_xor_sync(0xffffffffu, s0, 1);
    s0 += __shfl_xor_sync(0xffffffffu, s0, 2);
    s1 += __shfl_xor_sync(0xffffffffu, s1, 1);
    s1 += __shfl_xor_sync(0xffffffffu, s1, 2);
    const float inv0 = 1.0f / s0;
    const float inv1 = 1.0f / s1;

    // O = P V : P a-frags packed directly from the S C-frags (no smem).
    float oacc[4][4];
    #pragma unroll
    for (int nt = 0; nt < 4; ++nt)
        #pragma unroll
        for (int r = 0; r < 4; ++r) oacc[nt][r] = 0.0f;

    #pragma unroll
    for (int kt = 0; kt < 4; ++kt) {
        const uint32_t a0 = pack_h2(acc[2 * kt][0],     acc[2 * kt][1]);
        const uint32_t a1 = pack_h2(acc[2 * kt][2],     acc[2 * kt][3]);
        const uint32_t a2 = pack_h2(acc[2 * kt + 1][0], acc[2 * kt + 1][1]);
        const uint32_t a3 = pack_h2(acc[2 * kt + 1][2], acc[2 * kt + 1][3]);
        #pragma unroll
        for (int np = 0; np < 2; ++np) {
            uint32_t b0, b1, b2, b3;
            ldsm4t(b0, b1, b2, b3, uV + bV0 + kt * 16 * 80 + np * 32);
            mma_f16(oacc[2 * np],     a0, a1, a2, a3, b0, b1);
            mma_f16(oacc[2 * np + 1], a0, a1, a2, a3, b2, b3);
        }
    }

    // normalize, pack, store to slot 0 at [token][h*32+dim]
    __half* O = g_scrh[0] + base;
    #pragma unroll
    for (int nt = 0; nt < 4; ++nt) {
        const int col = nt * 8 + cb;
        *(uint32_t*)(O + (size_t)r0 * 512 + col) =
            pack_h2(oacc[nt][0] * inv0, oacc[nt][1] * inv0);
        *(uint32_t*)(O + (size_t)r1 * 512 + col) =
            pack_h2(oacc[nt][2] * inv1, oacc[nt][3] * inv1);
    }
}

// ---------------------------------------------------------------------------
// Launch
// ---------------------------------------------------------------------------
extern "C" void kernel_launch(void* const* d_in, const int* in_sizes, int n_in,
                              void* d_out, int out_size)
{
    const float* x      = (const float*)d_in[0];
    const float* mask   = (const float*)d_in[1];
    const float* dwq_w  = (const float*)d_in[2];
    const float* dwq_b  = (const float*)d_in[3];
    const float* pwq_w  = (const float*)d_in[4];
    const float* pwq_b  = (const float*)d_in[5];
    const float* dwk_w  = (const float*)d_in[6];
    const float* dwk_b  = (const float*)d_in[7];
    const float* pwk_w  = (const float*)d_in[8];
    const float* pwk_b  = (const float*)d_in[9];
    const float* dwv_w  = (const float*)d_in[10];
    const float* dwv_b  = (const float*)d_in[11];
    const float* pwv_w  = (const float*)d_in[12];
    const float* pwv_b  = (const float*)d_in[13];
    const float* pos    = (const float*)d_in[14];
    const float* proj_w = (const float*)d_in[15];
    const float* proj_b = (const float*)d_in[16];

    // 0. round weights to fp16 (w0 pre-scaled); precompute pos+mask
    prep_w<<<4096, 256>>>(pwq_w, pwk_w, pwv_w, proj_w);
    prep_pm<<<4096, 256>>>(mask, pos);

    // 1. depthwise 3x3 + ReLU -> slots 0,1,2 (fp16)
    dim3 gdw(4, BW);
    dw3_kernel<<<gdw, 256>>>(x, dwq_w, dwq_b, dwk_w, dwk_b, dwv_w, dwv_b);

    // 2. pointwise GEMMs (fp16 mma) -> slots 3,4,5
    dim3 gqkv(4, 512, 3);
    gemm_qkv<<<gqkv, 128>>>(pwq_b, pwk_b, pwv_b);

    // 3. fp16 tensor-core attention -> slot 0
    attn_h<<<BW * HEADS, 128>>>();

    // 4. output projection -> d_out (f32)
    dim3 gg(4, 512);
    gemm_proj<<<gg, 128>>>(proj_b, (float*)d_out);
}

// round 15
// speedup vs baseline: 1.1143x; 1.0162x over previous
#include <cuda_runtime.h>
#include <cuda_fp16.h>
#include <math.h>
#include <stdint.h>

// Problem constants
#define BW    1024          // windows (batch)
#define NTOK  64            // tokens per window (8x8)
#define CDIM  512           // channels
#define HEADS 16
#define HD    32            // head dim
#define BNC   (BW*NTOK*CDIM)

// Half scratch slots:
// slot 0: dwq -> later attention output
// slot 1: dwk   slot 2: dwv
// slot 3: q (pre-scaled)   slot 4: k     slot 5: v
__device__ __half g_scrh[6][BNC];
// fp16-rounded weights: 0=pwq (pre-scaled by 1/sqrt(32)), 1=pwk, 2=pwv, 3=proj
__device__ __half g_wh[4][CDIM*CDIM];
// precomputed pos+mask (fp32): [b][n][m]
__device__ float g_pm[BW * NTOK * NTOK];

#define ATTN_SCALE 0.17677669529663687f   // 1/sqrt(32)

// ---------------------------------------------------------------------------
// Weight prep
// ---------------------------------------------------------------------------
__global__ void prep_w(const float* __restrict__ w0, const float* __restrict__ w1,
                       const float* __restrict__ w2, const float* __restrict__ w3)
{
    int idx = blockIdx.x * 256 + threadIdx.x;
    int w = idx >> 18, j = idx & 262143;
    const float* s = (w == 0) ? w0 : (w == 1) ? w1 : (w == 2) ? w2 : w3;
    float v = s[j];
    if (w == 0) v *= ATTN_SCALE;
    g_wh[w][j] = __float2half_rn(v);
}

// pm[b][n][m] = mask[b][n][m] + pos[n][m]
__global__ void prep_pm(const float* __restrict__ mask, const float* __restrict__ pos)
{
    const int idx4 = (blockIdx.x * 256 + threadIdx.x) * 4;   // 4 M floats total
    const int rem = idx4 & 4095;
    float4 mv = *(const float4*)(mask + idx4);
    float4 pv = *(const float4*)(pos + rem);
    float4 o;
    o.x = mv.x + pv.x; o.y = mv.y + pv.y;
    o.z = mv.z + pv.z; o.w = mv.w + pv.w;
    *(float4*)(g_pm + idx4) = o;
}

__device__ __forceinline__ uint32_t pack_h2(float lo, float hi)
{
    __half2 h = __floats2half2_rn(lo, hi);
    return *(uint32_t*)&h;
}

// ---------------------------------------------------------------------------
// Kernel 1: fused depthwise 3x3 (+bias, ReLU) — R8 version (measured best).
// ---------------------------------------------------------------------------
__global__ void dw3_kernel(const float* __restrict__ x,
                           const float* __restrict__ wq, const float* __restrict__ bq,
                           const float* __restrict__ wk, const float* __restrict__ bk,
                           const float* __restrict__ wv, const float* __restrict__ bv)
{
    const int b   = blockIdx.y;
    const int c0  = blockIdx.x * 128;
    const int tid = threadIdx.x;            // 256 threads

    __shared__ float sx[64][128];
    const float* xb = x + (size_t)b * NTOK * CDIM;

    #pragma unroll
    for (int i = tid; i < 64 * 128; i += 256) {
        int n = i >> 7, c = i & 127;
        sx[n][c] = xb[n * CDIM + c0 + c];
    }
    __syncthreads();

    const int cl   = tid & 127;
    const int c    = c0 + cl;
    const int half = tid >> 7;

    float wqr[9], wkr[9], wvr[9];
    #pragma unroll
    for (int j = 0; j < 9; ++j) {
        wqr[j] = wq[c * 9 + j];
        wkr[j] = wk[c * 9 + j];
        wvr[j] = wv[c * 9 + j];
    }
    const float bqr = bq[c], bkr = bk[c], bvr = bv[c];

    __half* oq = g_scrh[0] + (size_t)b * NTOK * CDIM;
    __half* ok = g_scrh[1] + (size_t)b * NTOK * CDIM;
    __half* ov = g_scrh[2] + (size_t)b * NTOK * CDIM;

    #pragma unroll 4
    for (int nn = 0; nn < 32; ++nn) {
        int n = half * 32 + nn;
        int l = n >> 3, w = n & 7;
        float aq = bqr, ak = bkr, av = bvr;
        #pragma unroll
        for (int dl = -1; dl <= 1; ++dl) {
            #pragma unroll
            for (int dw = -1; dw <= 1; ++dw) {
                int ll = l + dl, ww = w + dw;
                if (ll < 0 || ll > 7 || ww < 0 || ww > 7) continue;
                float xv = sx[ll * 8 + ww][cl];
                int j = (dl + 1) * 3 + (dw + 1);
                aq += xv * wqr[j];
                ak += xv * wkr[j];
                av += xv * wvr[j];
            }
        }
        int idx = n * CDIM + c;
        oq[idx] = __float2half_rn(fmaxf(aq, 0.0f));
        ok[idx] = __float2half_rn(fmaxf(ak, 0.0f));
        ov[idx] = __float2half_rn(fmaxf(av, 0.0f));
    }
}

// ---------------------------------------------------------------------------
// mma.sync / ldmatrix helpers
// ---------------------------------------------------------------------------
__device__ __forceinline__ void mma_f16(float* d, uint32_t a0, uint32_t a1,
                                        uint32_t a2, uint32_t a3,
                                        uint32_t b0, uint32_t b1)
{
    asm volatile(
        "mma.sync.aligned.m16n8k16.row.col.f32.f16.f16.f32 "
        "{%0,%1,%2,%3}, {%4,%5,%6,%7}, {%8,%9}, {%0,%1,%2,%3};"
        : "+f"(d[0]), "+f"(d[1]), "+f"(d[2]), "+f"(d[3])
        : "r"(a0), "r"(a1), "r"(a2), "r"(a3), "r"(b0), "r"(b1));
}

__device__ __forceinline__ void ldsm4(uint32_t& r0, uint32_t& r1,
                                      uint32_t& r2, uint32_t& r3, uint32_t addr)
{
    asm volatile("ldmatrix.sync.aligned.m8n8.x4.shared.b16 {%0,%1,%2,%3}, [%4];"
                 : "=r"(r0), "=r"(r1), "=r"(r2), "=r"(r3) : "r"(addr));
}

__device__ __forceinline__ void ldsm4t(uint32_t& r0, uint32_t& r1,
                                       uint32_t& r2, uint32_t& r3, uint32_t addr)
{
    asm volatile("ldmatrix.sync.aligned.m8n8.x4.trans.shared.b16 {%0,%1,%2,%3}, [%4];"
                 : "=r"(r0), "=r"(r1), "=r"(r2), "=r"(r3) : "r"(addr));
}

__device__ __forceinline__ void cp16(uint32_t dst, const void* src)
{
    asm volatile("cp.async.cg.shared.global [%0], [%1], 16;"
                 :: "r"(dst), "l"(src) : "memory");
}

// ---------------------------------------------------------------------------
// fp16 GEMM body (R8 version, byte-exact — measured best): C = A @ W^T + bias
// CTA 128x128, 128 threads = 4 warps (2x2), warp tile 64x64, m16n8k16.
// K-chunk 16, 3-stage cp.async ring, one sync per chunk.
// Smem rows = 8 half2 data + pad -> pitch 12 half2 (bank-conflict-free).
// ---------------------------------------------------------------------------
#define PADH 12
#define HST  (128 * PADH)                 // half2 (=u32) per stage per matrix

__device__ __forceinline__ void gemm_body_h(const __half* __restrict__ A,
                                            const __half* __restrict__ W,
                                            const float* __restrict__ bias,
                                            float bscale,
                                            __half* __restrict__ Ch,
                                            float* __restrict__ Cf)
{
    __shared__ uint32_t smA[3 * HST];
    __shared__ uint32_t smB[3 * HST];

    const int tid  = threadIdx.x;           // 128 threads
    const int wid  = tid >> 5;
    const int lane = tid & 31;
    const int wm   = wid & 1;
    const int wn   = wid >> 1;
    const int m0 = blockIdx.y * 128;
    const int n0 = blockIdx.x * 128;

    const int lrow = tid >> 1;              // 0..63
    const int seg  = tid & 1;               // 8-half segment within k16

    const int qrow = lane >> 2;
    const int qcol = lane & 3;

    const uint32_t sAb = (uint32_t)__cvta_generic_to_shared(smA);
    const uint32_t sBb = (uint32_t)__cvta_generic_to_shared(smB);

    float acc[4][8][4];
    #pragma unroll
    for (int i = 0; i < 4; ++i)
        #pragma unroll
        for (int j = 0; j < 8; ++j)
            #pragma unroll
            for (int r = 0; r < 4; ++r) acc[i][j][r] = 0.0f;

    const __half* Ap = A + (size_t)(m0 + lrow) * 512 + seg * 8;
    const __half* Bp = W + (size_t)(n0 + lrow) * 512 + seg * 8;

    // prologue: stages 0,1
    #pragma unroll
    for (int st = 0; st < 2; ++st) {
        #pragma unroll
        for (int r = 0; r < 2; ++r) {
            uint32_t off = (uint32_t)(((st * 128 + lrow + r * 64) * PADH + seg * 4) * 4);
            cp16(sAb + off, Ap + (size_t)(r * 64) * 512 + st * 16);
            cp16(sBb + off, Bp + (size_t)(r * 64) * 512 + st * 16);
        }
        asm volatile("cp.async.commit_group;" ::: "memory");
    }

    int s = 0, p = 2;
    #pragma unroll 1
    for (int ch = 0; ch < 32; ++ch) {
        asm volatile("cp.async.wait_group 1;" ::: "memory");
        __syncthreads();

        if (ch < 30) {
            const int kb = (ch + 2) * 16;
            #pragma unroll
            for (int r = 0; r < 2; ++r) {
                uint32_t off = (uint32_t)(((p * 128 + lrow + r * 64) * PADH + seg * 4) * 4);
                cp16(sAb + off, Ap + (size_t)(r * 64) * 512 + kb);
                cp16(sBb + off, Bp + (size_t)(r * 64) * 512 + kb);
            }
        }
        asm volatile("cp.async.commit_group;" ::: "memory");

        const uint32_t* Ab = smA + s * HST;
        const uint32_t* Bb = smB + s * HST;

        uint32_t a[4][4];
        #pragma unroll
        for (int mi = 0; mi < 4; ++mi) {
            const int mr = wm * 64 + mi * 16 + qrow;
            a[mi][0] = Ab[mr * PADH + qcol];
            a[mi][1] = Ab[(mr + 8) * PADH + qcol];
            a[mi][2] = Ab[mr * PADH + qcol + 4];
            a[mi][3] = Ab[(mr + 8) * PADH + qcol + 4];
        }
        uint32_t bfr[8][2];
        #pragma unroll
        for (int ni = 0; ni < 8; ++ni) {
            const int nc = wn * 64 + ni * 8 + qrow;
            bfr[ni][0] = Bb[nc * PADH + qcol];
            bfr[ni][1] = Bb[nc * PADH + qcol + 4];
        }
        #pragma unroll
        for (int mi = 0; mi < 4; ++mi)
            #pragma unroll
            for (int ni = 0; ni < 8; ++ni)
                mma_f16(acc[mi][ni], a[mi][0], a[mi][1], a[mi][2], a[mi][3],
                        bfr[ni][0], bfr[ni][1]);

        s = (s == 2) ? 0 : s + 1;
        p = (p == 2) ? 0 : p + 1;
    }

    // Epilogue: bias (optionally scaled), half2 or float2 stores
    #pragma unroll
    for (int ni = 0; ni < 8; ++ni) {
        const int n = n0 + wn * 64 + ni * 8 + (qcol << 1);
        const float bx = bias[n] * bscale;
        const float by = bias[n + 1] * bscale;
        #pragma unroll
        for (int mi = 0; mi < 4; ++mi) {
            const int m = m0 + wm * 64 + mi * 16 + qrow;
            const float f0 = acc[mi][ni][0] + bx, f1 = acc[mi][ni][1] + by;
            const float f2 = acc[mi][ni][2] + bx, f3 = acc[mi][ni][3] + by;
            if (Ch) {
                *(uint32_t*)(Ch + (size_t)m * 512 + n)       = pack_h2(f0, f1);
                *(uint32_t*)(Ch + (size_t)(m + 8) * 512 + n) = pack_h2(f2, f3);
            } else {
                *(float2*)(Cf + (size_t)m * 512 + n)       = make_float2(f0, f1);
                *(float2*)(Cf + (size_t)(m + 8) * 512 + n) = make_float2(f2, f3);
            }
        }
    }
}

// QKV: grid.z selects slot (0,1,2) -> writes slots (3,4,5).
__global__ void __launch_bounds__(128, 3)
gemm_qkv(const float* __restrict__ bq, const float* __restrict__ bk,
         const float* __restrict__ bv)
{
    const int z = blockIdx.z;
    const float* bias = (z == 0) ? bq : (z == 1) ? bk : bv;
    const float bscale = (z == 0) ? ATTN_SCALE : 1.0f;
    gemm_body_h(g_scrh[z], g_wh[z], bias, bscale, g_scrh[3 + z], nullptr);
}

__global__ void __launch_bounds__(128, 3)
gemm_proj(const float* __restrict__ bias, float* __restrict__ C)
{
    gemm_body_h(g_scrh[0], g_wh[3], bias, 1.0f, nullptr, C);
}

// ---------------------------------------------------------------------------
// Kernel 3: fp16 tensor-core attention. One CTA = 4 heads of one window,
// processed sequentially; pos+mask rows live in REGISTERS across heads
// (warp->row mapping is head-invariant) -> pm gmem traffic cut 4x.
// Per-head compute identical to the measured-good R12 version.
// ---------------------------------------------------------------------------
__global__ void __launch_bounds__(128)
attn_h()
{
    const int blk = blockIdx.x;            // 4096 blocks
    const int b  = blk >> 2;
    const int h0 = (blk & 3) * 4;          // first head of this CTA's group
    const int tid  = threadIdx.x;
    const int wid  = tid >> 5;
    const int lane = tid & 31;
    const int qrow = lane >> 2;
    const int qcol = lane & 3;
    const int mat  = lane >> 3;
    const int rr   = lane & 7;

    __shared__ uint32_t Qs[64 * 20];   // [token][16 half2 + pad], pitch 80B
    __shared__ uint32_t Ks[64 * 20];
    __shared__ uint32_t Vs[64 * 20];

    const __half* Q = g_scrh[3];
    const __half* K = g_scrh[4];
    const __half* V = g_scrh[5];
    const size_t wbase = (size_t)b * 64 * 512;

    const uint32_t uQ = (uint32_t)__cvta_generic_to_shared(Qs);
    const uint32_t uK = (uint32_t)__cvta_generic_to_shared(Ks);
    const uint32_t uV = (uint32_t)__cvta_generic_to_shared(Vs);

    const int m0 = wid * 16;
    const uint32_t aQ0 = (uint32_t)((m0 + ((mat & 1) << 3) + rr) * 80 + ((mat >> 1) << 4));
    const uint32_t bK0 = (uint32_t)((((mat >> 1) << 3) + rr) * 80 + ((mat & 1) << 4));
    const uint32_t bV0 = (uint32_t)((((mat & 1) << 3) + rr) * 80 + ((mat >> 1) << 4));

    // pos+mask rows for this thread's two C-fragment rows: load ONCE.
    const int r0 = m0 + qrow, r1 = r0 + 8;
    const int cb = qcol * 2;
    float2 pm0[8], pm1[8];
    {
        const float* pmb = g_pm + (size_t)b * 4096;
        #pragma unroll
        for (int nt = 0; nt < 8; ++nt) {
            const int col = nt * 8 + cb;
            pm0[nt] = *(const float2*)(pmb + r0 * 64 + col);
            pm1[nt] = *(const float2*)(pmb + r1 * 64 + col);
        }
    }

    #pragma unroll 1
    for (int hh = 0; hh < 4; ++hh) {
        const size_t base = wbase + (h0 + hh) * 32;

        if (hh > 0) __syncthreads();   // prior head done reading smem
        #pragma unroll
        for (int i = tid; i < 256; i += 128) {
            const int t = i >> 2, g = i & 3;
            const size_t gofs = base + (size_t)t * 512 + g * 8;
            *(uint4*)((char*)Qs + t * 80 + g * 16) = *(const uint4*)(Q + gofs);
            *(uint4*)((char*)Ks + t * 80 + g * 16) = *(const uint4*)(K + gofs);
            *(uint4*)((char*)Vs + t * 80 + g * 16) = *(const uint4*)(V + gofs);
        }
        __syncthreads();

        // S = Q K^T  (warp rows m0..m0+15; q pre-scaled)
        float acc[8][4];
        #pragma unroll
        for (int nt = 0; nt < 8; ++nt)
            #pragma unroll
            for (int r = 0; r < 4; ++r) acc[nt][r] = 0.0f;

        #pragma unroll
        for (int kt = 0; kt < 2; ++kt) {
            uint32_t a0, a1, a2, a3;
            ldsm4(a0, a1, a2, a3, uQ + aQ0 + kt * 32);
            #pragma unroll
            for (int pi = 0; pi < 4; ++pi) {
                uint32_t b0, b1, b2, b3;
                ldsm4(b0, b1, b2, b3, uK + bK0 + pi * 1280 + kt * 32);
                mma_f16(acc[2 * pi],     a0, a1, a2, a3, b0, b1);
                mma_f16(acc[2 * pi + 1], a0, a1, a2, a3, b2, b3);
            }
        }

        // + pm (registers); fragment softmax (quad shfl reductions)
        float mx0 = -1e30f, mx1 = -1e30f;
        #pragma unroll
        for (int nt = 0; nt < 8; ++nt) {
            acc[nt][0] += pm0[nt].x;
            acc[nt][1] += pm0[nt].y;
            acc[nt][2] += pm1[nt].x;
            acc[nt][3] += pm1[nt].y;
            mx0 = fmaxf(mx0, fmaxf(acc[nt][0], acc[nt][1]));
            mx1 = fmaxf(mx1, fmaxf(acc[nt][2], acc[nt][3]));
        }
        mx0 = fmaxf(mx0, __shfl_xor_sync(0xffffffffu, mx0, 1));
        mx0 = fmaxf(mx0, __shfl_xor_sync(0xffffffffu, mx0, 2));
        mx1 = fmaxf(mx1, __shfl_xor_sync(0xffffffffu, mx1, 1));
        mx1 = fmaxf(mx1, __shfl_xor_sync(0xffffffffu, mx1, 2));

        float s0 = 0.0f, s1 = 0.0f;
        #pragma unroll
        for (int nt = 0; nt < 8; ++nt) {
            acc[nt][0] = __expf(acc[nt][0] - mx0);
            acc[nt][1] = __expf(acc[nt][1] - mx0);
            acc[nt][2] = __expf(acc[nt][2] - mx1);
            acc[nt][3] = __expf(acc[nt][3] - mx1);
            s0 += acc[nt][0] + acc[nt][1];
            s1 += acc[nt][2] + acc[nt][3];
        }
        s0 += __shfl_xor_sync(0xffffffffu, s0, 1);
        s0 += __shfl_xor_sync(0xffffffffu, s0, 2);
        s1 += __shfl_xor_sync(0xffffffffu, s1, 1);
        s1 += __shfl_xor_sync(0xffffffffu, s1, 2);
        const float inv0 = 1.0f / s0;
        const float inv1 = 1.0f / s1;

        // O = P V : P a-frags packed directly from the S C-frags (no smem).
        float oacc[4][4];
        #pragma unroll
        for (int nt = 0; nt < 4; ++nt)
            #pragma unroll
            for (int r = 0; r < 4; ++r) oacc[nt][r] = 0.0f;

        #pragma unroll
        for (int kt = 0; kt < 4; ++kt) {
            const uint32_t a0 = pack_h2(acc[2 * kt][0],     acc[2 * kt][1]);
            const uint32_t a1 = pack_h2(acc[2 * kt][2],     acc[2 * kt][3]);
            const uint32_t a2 = pack_h2(acc[2 * kt + 1][0], acc[2 * kt + 1][1]);
            const uint32_t a3 = pack_h2(acc[2 * kt + 1][2], acc[2 * kt + 1][3]);
            #pragma unroll
            for (int np = 0; np < 2; ++np) {
                uint32_t b0, b1, b2, b3;
                ldsm4t(b0, b1, b2, b3, uV + bV0 + kt * 16 * 80 + np * 32);
                mma_f16(oacc[2 * np],     a0, a1, a2, a3, b0, b1);
                mma_f16(oacc[2 * np + 1], a0, a1, a2, a3, b2, b3);
            }
        }

        // normalize, pack, store to slot 0 at [token][h*32+dim]
        __half* O = g_scrh[0] + base;
        #pragma unroll
        for (int nt = 0; nt < 4; ++nt) {
            const int col = nt * 8 + cb;
            *(uint32_t*)(O + (size_t)r0 * 512 + col) =
                pack_h2(oacc[nt][0] * inv0, oacc[nt][1] * inv0);
            *(uint32_t*)(O + (size_t)r1 * 512 + col) =
                pack_h2(oacc[nt][2] * inv1, oacc[nt][3] * inv1);
        }
    }
}

// ---------------------------------------------------------------------------
// Launch
// ---------------------------------------------------------------------------
extern "C" void kernel_launch(void* const* d_in, const int* in_sizes, int n_in,
                              void* d_out, int out_size)
{
    const float* x      = (const float*)d_in[0];
    const float* mask   = (const float*)d_in[1];
    const float* dwq_w  = (const float*)d_in[2];
    const float* dwq_b  = (const float*)d_in[3];
    const float* pwq_w  = (const float*)d_in[4];
    const float* pwq_b  = (const float*)d_in[5];
    const float* dwk_w  = (const float*)d_in[6];
    const float* dwk_b  = (const float*)d_in[7];
    const float* pwk_w  = (const float*)d_in[8];
    const float* pwk_b  = (const float*)d_in[9];
    const float* dwv_w  = (const float*)d_in[10];
    const float* dwv_b  = (const float*)d_in[11];
    const float* pwv_w  = (const float*)d_in[12];
    const float* pwv_b  = (const float*)d_in[13];
    const float* pos    = (const float*)d_in[14];
    const float* proj_w = (const float*)d_in[15];
    const float* proj_b = (const float*)d_in[16];

    // 0. round weights to fp16 (w0 pre-scaled); precompute pos+mask
    prep_w<<<4096, 256>>>(pwq_w, pwk_w, pwv_w, proj_w);
    prep_pm<<<4096, 256>>>(mask, pos);

    // 1. depthwise 3x3 + ReLU -> slots 0,1,2 (fp16)
    dim3 gdw(4, BW);
    dw3_kernel<<<gdw, 256>>>(x, dwq_w, dwq_b, dwk_w, dwk_b, dwv_w, dwv_b);

    // 2. pointwise GEMMs (fp16 mma) -> slots 3,4,5
    dim3 gqkv(4, 512, 3);
    gemm_qkv<<<gqkv, 128>>>(pwq_b, pwk_b, pwv_b);

    // 3. fp16 tensor-core attention (4 heads per CTA) -> slot 0
    attn_h<<<BW * 4, 128>>>();

    // 4. output projection -> d_out (f32)
    dim3 gg(4, 512);
    gemm_proj<<<gg, 128>>>(proj_b, (float*)d_out);
}

// round 16
// speedup vs baseline: 1.1165x; 1.0020x over previous
#include <cuda_runtime.h>
#include <cuda_fp16.h>
#include <math.h>
#include <stdint.h>

// Problem constants
#define BW    1024          // windows (batch)
#define NTOK  64            // tokens per window (8x8)
#define CDIM  512           // channels
#define HEADS 16
#define HD    32            // head dim
#define BNC   (BW*NTOK*CDIM)

// Half scratch slots:
// slot 0: dwq -> later attention output
// slot 1: dwk   slot 2: dwv
// slot 3: q (pre-scaled)   slot 4: k     slot 5: v
__device__ __half g_scrh[6][BNC];
// fp16-rounded weights: 0=pwq (pre-scaled by 1/sqrt(32)), 1=pwk, 2=pwv, 3=proj
__device__ __half g_wh[4][CDIM*CDIM];
// precomputed pos+mask (fp32): [b][n][m]
__device__ float g_pm[BW * NTOK * NTOK];

#define ATTN_SCALE 0.17677669529663687f   // 1/sqrt(32)

// ---------------------------------------------------------------------------
// Merged prep: blocks [0,4096) round weights to fp16 (w0 pre-scaled);
// blocks [4096,8192) compute pm = mask + pos (float4).
// ---------------------------------------------------------------------------
__global__ void prep_all(const float* __restrict__ w0, const float* __restrict__ w1,
                         const float* __restrict__ w2, const float* __restrict__ w3,
                         const float* __restrict__ mask, const float* __restrict__ pos)
{
    if (blockIdx.x < 4096) {
        int idx = blockIdx.x * 256 + threadIdx.x;
        int w = idx >> 18, j = idx & 262143;
        const float* s = (w == 0) ? w0 : (w == 1) ? w1 : (w == 2) ? w2 : w3;
        float v = s[j];
        if (w == 0) v *= ATTN_SCALE;
        g_wh[w][j] = __float2half_rn(v);
    } else {
        const int idx4 = ((blockIdx.x - 4096) * 256 + threadIdx.x) * 4;
        const int rem = idx4 & 4095;
        float4 mv = *(const float4*)(mask + idx4);
        float4 pv = *(const float4*)(pos + rem);
        float4 o;
        o.x = mv.x + pv.x; o.y = mv.y + pv.y;
        o.z = mv.z + pv.z; o.w = mv.w + pv.w;
        *(float4*)(g_pm + idx4) = o;
    }
}

__device__ __forceinline__ uint32_t pack_h2(float lo, float hi)
{
    __half2 h = __floats2half2_rn(lo, hi);
    return *(uint32_t*)&h;
}

// ---------------------------------------------------------------------------
// Kernel 1: fused depthwise 3x3 (+bias, ReLU) — R8 version (measured best).
// ---------------------------------------------------------------------------
__global__ void dw3_kernel(const float* __restrict__ x,
                           const float* __restrict__ wq, const float* __restrict__ bq,
                           const float* __restrict__ wk, const float* __restrict__ bk,
                           const float* __restrict__ wv, const float* __restrict__ bv)
{
    const int b   = blockIdx.y;
    const int c0  = blockIdx.x * 128;
    const int tid = threadIdx.x;            // 256 threads

    __shared__ float sx[64][128];
    const float* xb = x + (size_t)b * NTOK * CDIM;

    #pragma unroll
    for (int i = tid; i < 64 * 128; i += 256) {
        int n = i >> 7, c = i & 127;
        sx[n][c] = xb[n * CDIM + c0 + c];
    }
    __syncthreads();

    const int cl   = tid & 127;
    const int c    = c0 + cl;
    const int half = tid >> 7;

    float wqr[9], wkr[9], wvr[9];
    #pragma unroll
    for (int j = 0; j < 9; ++j) {
        wqr[j] = wq[c * 9 + j];
        wkr[j] = wk[c * 9 + j];
        wvr[j] = wv[c * 9 + j];
    }
    const float bqr = bq[c], bkr = bk[c], bvr = bv[c];

    __half* oq = g_scrh[0] + (size_t)b * NTOK * CDIM;
    __half* ok = g_scrh[1] + (size_t)b * NTOK * CDIM;
    __half* ov = g_scrh[2] + (size_t)b * NTOK * CDIM;

    #pragma unroll 4
    for (int nn = 0; nn < 32; ++nn) {
        int n = half * 32 + nn;
        int l = n >> 3, w = n & 7;
        float aq = bqr, ak = bkr, av = bvr;
        #pragma unroll
        for (int dl = -1; dl <= 1; ++dl) {
            #pragma unroll
            for (int dw = -1; dw <= 1; ++dw) {
                int ll = l + dl, ww = w + dw;
                if (ll < 0 || ll > 7 || ww < 0 || ww > 7) continue;
                float xv = sx[ll * 8 + ww][cl];
                int j = (dl + 1) * 3 + (dw + 1);
                aq += xv * wqr[j];
                ak += xv * wkr[j];
                av += xv * wvr[j];
            }
        }
        int idx = n * CDIM + c;
        oq[idx] = __float2half_rn(fmaxf(aq, 0.0f));
        ok[idx] = __float2half_rn(fmaxf(ak, 0.0f));
        ov[idx] = __float2half_rn(fmaxf(av, 0.0f));
    }
}

// ---------------------------------------------------------------------------
// mma.sync / ldmatrix helpers
// ---------------------------------------------------------------------------
__device__ __forceinline__ void mma_f16(float* d, uint32_t a0, uint32_t a1,
                                        uint32_t a2, uint32_t a3,
                                        uint32_t b0, uint32_t b1)
{
    asm volatile(
        "mma.sync.aligned.m16n8k16.row.col.f32.f16.f16.f32 "
        "{%0,%1,%2,%3}, {%4,%5,%6,%7}, {%8,%9}, {%0,%1,%2,%3};"
        : "+f"(d[0]), "+f"(d[1]), "+f"(d[2]), "+f"(d[3])
        : "r"(a0), "r"(a1), "r"(a2), "r"(a3), "r"(b0), "r"(b1));
}

__device__ __forceinline__ void ldsm4(uint32_t& r0, uint32_t& r1,
                                      uint32_t& r2, uint32_t& r3, uint32_t addr)
{
    asm volatile("ldmatrix.sync.aligned.m8n8.x4.shared.b16 {%0,%1,%2,%3}, [%4];"
                 : "=r"(r0), "=r"(r1), "=r"(r2), "=r"(r3) : "r"(addr));
}

__device__ __forceinline__ void ldsm4t(uint32_t& r0, uint32_t& r1,
                                       uint32_t& r2, uint32_t& r3, uint32_t addr)
{
    asm volatile("ldmatrix.sync.aligned.m8n8.x4.trans.shared.b16 {%0,%1,%2,%3}, [%4];"
                 : "=r"(r0), "=r"(r1), "=r"(r2), "=r"(r3) : "r"(addr));
}

__device__ __forceinline__ void cp16(uint32_t dst, const void* src)
{
    asm volatile("cp.async.cg.shared.global [%0], [%1], 16;"
                 :: "r"(dst), "l"(src) : "memory");
}

// ---------------------------------------------------------------------------
// fp16 GEMM body (R8 version, byte-exact — measured best): C = A @ W^T + bias
// CTA 128x128, 128 threads = 4 warps (2x2), warp tile 64x64, m16n8k16.
// K-chunk 16, 3-stage cp.async ring, one sync per chunk.
// Smem rows = 8 half2 data + pad -> pitch 12 half2 (bank-conflict-free).
// ---------------------------------------------------------------------------
#define PADH 12
#define HST  (128 * PADH)                 // half2 (=u32) per stage per matrix

__device__ __forceinline__ void gemm_body_h(const __half* __restrict__ A,
                                            const __half* __restrict__ W,
                                            const float* __restrict__ bias,
                                            float bscale,
                                            __half* __restrict__ Ch,
                                            float* __restrict__ Cf)
{
    __shared__ uint32_t smA[3 * HST];
    __shared__ uint32_t smB[3 * HST];

    const int tid  = threadIdx.x;           // 128 threads
    const int wid  = tid >> 5;
    const int lane = tid & 31;
    const int wm   = wid & 1;
    const int wn   = wid >> 1;
    const int m0 = blockIdx.y * 128;
    const int n0 = blockIdx.x * 128;

    const int lrow = tid >> 1;              // 0..63
    const int seg  = tid & 1;               // 8-half segment within k16

    const int qrow = lane >> 2;
    const int qcol = lane & 3;

    const uint32_t sAb = (uint32_t)__cvta_generic_to_shared(smA);
    const uint32_t sBb = (uint32_t)__cvta_generic_to_shared(smB);

    float acc[4][8][4];
    #pragma unroll
    for (int i = 0; i < 4; ++i)
        #pragma unroll
        for (int j = 0; j < 8; ++j)
            #pragma unroll
            for (int r = 0; r < 4; ++r) acc[i][j][r] = 0.0f;

    const __half* Ap = A + (size_t)(m0 + lrow) * 512 + seg * 8;
    const __half* Bp = W + (size_t)(n0 + lrow) * 512 + seg * 8;

    // prologue: stages 0,1
    #pragma unroll
    for (int st = 0; st < 2; ++st) {
        #pragma unroll
        for (int r = 0; r < 2; ++r) {
            uint32_t off = (uint32_t)(((st * 128 + lrow + r * 64) * PADH + seg * 4) * 4);
            cp16(sAb + off, Ap + (size_t)(r * 64) * 512 + st * 16);
            cp16(sBb + off, Bp + (size_t)(r * 64) * 512 + st * 16);
        }
        asm volatile("cp.async.commit_group;" ::: "memory");
    }

    int s = 0, p = 2;
    #pragma unroll 1
    for (int ch = 0; ch < 32; ++ch) {
        asm volatile("cp.async.wait_group 1;" ::: "memory");
        __syncthreads();

        if (ch < 30) {
            const int kb = (ch + 2) * 16;
            #pragma unroll
            for (int r = 0; r < 2; ++r) {
                uint32_t off = (uint32_t)(((p * 128 + lrow + r * 64) * PADH + seg * 4) * 4);
                cp16(sAb + off, Ap + (size_t)(r * 64) * 512 + kb);
                cp16(sBb + off, Bp + (size_t)(r * 64) * 512 + kb);
            }
        }
        asm volatile("cp.async.commit_group;" ::: "memory");

        const uint32_t* Ab = smA + s * HST;
        const uint32_t* Bb = smB + s * HST;

        uint32_t a[4][4];
        #pragma unroll
        for (int mi = 0; mi < 4; ++mi) {
            const int mr = wm * 64 + mi * 16 + qrow;
            a[mi][0] = Ab[mr * PADH + qcol];
            a[mi][1] = Ab[(mr + 8) * PADH + qcol];
            a[mi][2] = Ab[mr * PADH + qcol + 4];
            a[mi][3] = Ab[(mr + 8) * PADH + qcol + 4];
        }
        uint32_t bfr[8][2];
        #pragma unroll
        for (int ni = 0; ni < 8; ++ni) {
            const int nc = wn * 64 + ni * 8 + qrow;
            bfr[ni][0] = Bb[nc * PADH + qcol];
            bfr[ni][1] = Bb[nc * PADH + qcol + 4];
        }
        #pragma unroll
        for (int mi = 0; mi < 4; ++mi)
            #pragma unroll
            for (int ni = 0; ni < 8; ++ni)
                mma_f16(acc[mi][ni], a[mi][0], a[mi][1], a[mi][2], a[mi][3],
                        bfr[ni][0], bfr[ni][1]);

        s = (s == 2) ? 0 : s + 1;
        p = (p == 2) ? 0 : p + 1;
    }

    // Epilogue: bias (optionally scaled), half2 or float2 stores
    #pragma unroll
    for (int ni = 0; ni < 8; ++ni) {
        const int n = n0 + wn * 64 + ni * 8 + (qcol << 1);
        const float bx = bias[n] * bscale;
        const float by = bias[n + 1] * bscale;
        #pragma unroll
        for (int mi = 0; mi < 4; ++mi) {
            const int m = m0 + wm * 64 + mi * 16 + qrow;
            const float f0 = acc[mi][ni][0] + bx, f1 = acc[mi][ni][1] + by;
            const float f2 = acc[mi][ni][2] + bx, f3 = acc[mi][ni][3] + by;
            if (Ch) {
                *(uint32_t*)(Ch + (size_t)m * 512 + n)       = pack_h2(f0, f1);
                *(uint32_t*)(Ch + (size_t)(m + 8) * 512 + n) = pack_h2(f2, f3);
            } else {
                *(float2*)(Cf + (size_t)m * 512 + n)       = make_float2(f0, f1);
                *(float2*)(Cf + (size_t)(m + 8) * 512 + n) = make_float2(f2, f3);
            }
        }
    }
}

// QKV: grid.z selects slot (0,1,2) -> writes slots (3,4,5).
__global__ void __launch_bounds__(128, 3)
gemm_qkv(const float* __restrict__ bq, const float* __restrict__ bk,
         const float* __restrict__ bv)
{
    const int z = blockIdx.z;
    const float* bias = (z == 0) ? bq : (z == 1) ? bk : bv;
    const float bscale = (z == 0) ? ATTN_SCALE : 1.0f;
    gemm_body_h(g_scrh[z], g_wh[z], bias, bscale, g_scrh[3 + z], nullptr);
}

__global__ void __launch_bounds__(128, 3)
gemm_proj(const float* __restrict__ bias, float* __restrict__ C)
{
    gemm_body_h(g_scrh[0], g_wh[3], bias, 1.0f, nullptr, C);
}

// ---------------------------------------------------------------------------
// Kernel 3: fp16 tensor-core attention. One CTA = 8 heads of one window,
// processed sequentially; pos+mask rows live in REGISTERS across heads
// (warp->row mapping is head-invariant) -> pm gmem traffic cut 8x.
// Per-head compute identical to the measured-good R12/R15 version.
// ---------------------------------------------------------------------------
__global__ void __launch_bounds__(128)
attn_h()
{
    const int blk = blockIdx.x;            // 2048 blocks
    const int b  = blk >> 1;
    const int h0 = (blk & 1) * 8;          // first head of this CTA's group
    const int tid  = threadIdx.x;
    const int wid  = tid >> 5;
    const int lane = tid & 31;
    const int qrow = lane >> 2;
    const int qcol = lane & 3;
    const int mat  = lane >> 3;
    const int rr   = lane & 7;

    __shared__ uint32_t Qs[64 * 20];   // [token][16 half2 + pad], pitch 80B
    __shared__ uint32_t Ks[64 * 20];
    __shared__ uint32_t Vs[64 * 20];

    const __half* Q = g_scrh[3];
    const __half* K = g_scrh[4];
    const __half* V = g_scrh[5];
    const size_t wbase = (size_t)b * 64 * 512;

    const uint32_t uQ = (uint32_t)__cvta_generic_to_shared(Qs);
    const uint32_t uK = (uint32_t)__cvta_generic_to_shared(Ks);
    const uint32_t uV = (uint32_t)__cvta_generic_to_shared(Vs);

    const int m0 = wid * 16;
    const uint32_t aQ0 = (uint32_t)((m0 + ((mat & 1) << 3) + rr) * 80 + ((mat >> 1) << 4));
    const uint32_t bK0 = (uint32_t)((((mat >> 1) << 3) + rr) * 80 + ((mat & 1) << 4));
    const uint32_t bV0 = (uint32_t)((((mat & 1) << 3) + rr) * 80 + ((mat >> 1) << 4));

    // pos+mask rows for this thread's two C-fragment rows: load ONCE.
    const int r0 = m0 + qrow, r1 = r0 + 8;
    const int cb = qcol * 2;
    float2 pm0[8], pm1[8];
    {
        const float* pmb = g_pm + (size_t)b * 4096;
        #pragma unroll
        for (int nt = 0; nt < 8; ++nt) {
            const int col = nt * 8 + cb;
            pm0[nt] = *(const float2*)(pmb + r0 * 64 + col);
            pm1[nt] = *(const float2*)(pmb + r1 * 64 + col);
        }
    }

    #pragma unroll 1
    for (int hh = 0; hh < 8; ++hh) {
        const size_t base = wbase + (h0 + hh) * 32;

        if (hh > 0) __syncthreads();   // prior head done reading smem
        #pragma unroll
        for (int i = tid; i < 256; i += 128) {
            const int t = i >> 2, g = i & 3;
            const size_t gofs = base + (size_t)t * 512 + g * 8;
            *(uint4*)((char*)Qs + t * 80 + g * 16) = *(const uint4*)(Q + gofs);
            *(uint4*)((char*)Ks + t * 80 + g * 16) = *(const uint4*)(K + gofs);
            *(uint4*)((char*)Vs + t * 80 + g * 16) = *(const uint4*)(V + gofs);
        }
        __syncthreads();

        // S = Q K^T  (warp rows m0..m0+15; q pre-scaled)
        float acc[8][4];
        #pragma unroll
        for (int nt = 0; nt < 8; ++nt)
            #pragma unroll
            for (int r = 0; r < 4; ++r) acc[nt][r] = 0.0f;

        #pragma unroll
        for (int kt = 0; kt < 2; ++kt) {
            uint32_t a0, a1, a2, a3;
            ldsm4(a0, a1, a2, a3, uQ + aQ0 + kt * 32);
            #pragma unroll
            for (int pi = 0; pi < 4; ++pi) {
                uint32_t b0, b1, b2, b3;
                ldsm4(b0, b1, b2, b3, uK + bK0 + pi * 1280 + kt * 32);
                mma_f16(acc[2 * pi],     a0, a1, a2, a3, b0, b1);
                mma_f16(acc[2 * pi + 1], a0, a1, a2, a3, b2, b3);
            }
        }

        // + pm (registers); fragment softmax (quad shfl reductions)
        float mx0 = -1e30f, mx1 = -1e30f;
        #pragma unroll
        for (int nt = 0; nt < 8; ++nt) {
            acc[nt][0] += pm0[nt].x;
            acc[nt][1] += pm0[nt].y;
            acc[nt][2] += pm1[nt].x;
            acc[nt][3] += pm1[nt].y;
            mx0 = fmaxf(mx0, fmaxf(acc[nt][0], acc[nt][1]));
            mx1 = fmaxf(mx1, fmaxf(acc[nt][2], acc[nt][3]));
        }
        mx0 = fmaxf(mx0, __shfl_xor_sync(0xffffffffu, mx0, 1));
        mx0 = fmaxf(mx0, __shfl_xor_sync(0xffffffffu, mx0, 2));
        mx1 = fmaxf(mx1, __shfl_xor_sync(0xffffffffu, mx1, 1));
        mx1 = fmaxf(mx1, __shfl_xor_sync(0xffffffffu, mx1, 2));

        float s0 = 0.0f, s1 = 0.0f;
        #pragma unroll
        for (int nt = 0; nt < 8; ++nt) {
            acc[nt][0] = __expf(acc[nt][0] - mx0);
            acc[nt][1] = __expf(acc[nt][1] - mx0);
            acc[nt][2] = __expf(acc[nt][2] - mx1);
            acc[nt][3] = __expf(acc[nt][3] - mx1);
            s0 += acc[nt][0] + acc[nt][1];
            s1 += acc[nt][2] + acc[nt][3];
        }
        s0 += __shfl_xor_sync(0xffffffffu, s0, 1);
        s0 += __shfl_xor_sync(0xffffffffu, s0, 2);
        s1 += __shfl_xor_sync(0xffffffffu, s1, 1);
        s1 += __shfl_xor_sync(0xffffffffu, s1, 2);
        const float inv0 = 1.0f / s0;
        const float inv1 = 1.0f / s1;

        // O = P V : P a-frags packed directly from the S C-frags (no smem).
        float oacc[4][4];
        #pragma unroll
        for (int nt = 0; nt < 4; ++nt)
            #pragma unroll
            for (int r = 0; r < 4; ++r) oacc[nt][r] = 0.0f;

        #pragma unroll
        for (int kt = 0; kt < 4; ++kt) {
            const uint32_t a0 = pack_h2(acc[2 * kt][0],     acc[2 * kt][1]);
            const uint32_t a1 = pack_h2(acc[2 * kt][2],     acc[2 * kt][3]);
            const uint32_t a2 = pack_h2(acc[2 * kt + 1][0], acc[2 * kt + 1][1]);
            const uint32_t a3 = pack_h2(acc[2 * kt + 1][2], acc[2 * kt + 1][3]);
            #pragma unroll
            for (int np = 0; np < 2; ++np) {
                uint32_t b0, b1, b2, b3;
                ldsm4t(b0, b1, b2, b3, uV + bV0 + kt * 16 * 80 + np * 32);
                mma_f16(oacc[2 * np],     a0, a1, a2, a3, b0, b1);
                mma_f16(oacc[2 * np + 1], a0, a1, a2, a3, b2, b3);
            }
        }

        // normalize, pack, store to slot 0 at [token][h*32+dim]
        __half* O = g_scrh[0] + base;
        #pragma unroll
        for (int nt = 0; nt < 4; ++nt) {
            const int col = nt * 8 + cb;
            *(uint32_t*)(O + (size_t)r0 * 512 + col) =
                pack_h2(oacc[nt][0] * inv0, oacc[nt][1] * inv0);
            *(uint32_t*)(O + (size_t)r1 * 512 + col) =
                pack_h2(oacc[nt][2] * inv1, oacc[nt][3] * inv1);
        }
    }
}

// ---------------------------------------------------------------------------
// Launch
// ---------------------------------------------------------------------------
extern "C" void kernel_launch(void* const* d_in, const int* in_sizes, int n_in,
                              void* d_out, int out_size)
{
    const float* x      = (const float*)d_in[0];
    const float* mask   = (const float*)d_in[1];
    const float* dwq_w  = (const float*)d_in[2];
    const float* dwq_b  = (const float*)d_in[3];
    const float* pwq_w  = (const float*)d_in[4];
    const float* pwq_b  = (const float*)d_in[5];
    const float* dwk_w  = (const float*)d_in[6];
    const float* dwk_b  = (const float*)d_in[7];
    const float* pwk_w  = (const float*)d_in[8];
    const float* pwk_b  = (const float*)d_in[9];
    const float* dwv_w  = (const float*)d_in[10];
    const float* dwv_b  = (const float*)d_in[11];
    const float* pwv_w  = (const float*)d_in[12];
    const float* pwv_b  = (const float*)d_in[13];
    const float* pos    = (const float*)d_in[14];
    const float* proj_w = (const float*)d_in[15];
    const float* proj_b = (const float*)d_in[16];

    // 0. merged prep: fp16 weights (w0 pre-scaled) + pos+mask
    prep_all<<<8192, 256>>>(pwq_w, pwk_w, pwv_w, proj_w, mask, pos);

    // 1. depthwise 3x3 + ReLU -> slots 0,1,2 (fp16)
    dim3 gdw(4, BW);
    dw3_kernel<<<gdw, 256>>>(x, dwq_w, dwq_b, dwk_w, dwk_b, dwv_w, dwv_b);

    // 2. pointwise GEMMs (fp16 mma) -> slots 3,4,5
    dim3 gqkv(4, 512, 3);
    gemm_qkv<<<gqkv, 128>>>(pwq_b, pwk_b, pwv_b);

    // 3. fp16 tensor-core attention (8 heads per CTA) -> slot 0
    attn_h<<<BW * 2, 128>>>();

    // 4. output projection -> d_out (f32)
    dim3 gg(4, 512);
    gemm_proj<<<gg, 128>>>(proj_b, (float*)d_out);
}

// round 17
// speedup vs baseline: 1.1352x; 1.0167x over previous
#include <cuda_runtime.h>
#include <cuda_fp16.h>
#include <math.h>
#include <stdint.h>

// Problem constants
#define BW    1024          // windows (batch)
#define NTOK  64            // tokens per window (8x8)
#define CDIM  512           // channels
#define HEADS 16
#define HD    32            // head dim
#define BNC   (BW*NTOK*CDIM)

// Half scratch slots:
// slot 0: dwq -> later attention output
// slot 1: dwk   slot 2: dwv
// slot 3: q (pre-scaled)   slot 4: k     slot 5: v
__device__ __half g_scrh[6][BNC];
// fp16-rounded weights: 0=pwq (pre-scaled by 1/sqrt(32)), 1=pwk, 2=pwv, 3=proj
__device__ __half g_wh[4][CDIM*CDIM];
// precomputed pos+mask (fp32): [b][n][m]
__device__ float g_pm[BW * NTOK * NTOK];

#define ATTN_SCALE 0.17677669529663687f   // 1/sqrt(32)

__device__ __forceinline__ uint32_t pack_h2(float lo, float hi)
{
    __half2 h = __floats2half2_rn(lo, hi);
    return *(uint32_t*)&h;
}

// ---------------------------------------------------------------------------
// Merged prep + depthwise kernel. Independent work in one launch:
//   blocks [0,4096):      dw3 3x3 depthwise (+bias, ReLU) -> slots 0,1,2
//   blocks [4096,8192):   fp16 weight rounding (w0 pre-scaled)
//   blocks [8192,12288):  pm = mask + pos
// ---------------------------------------------------------------------------
__global__ void prep_dw3(const float* __restrict__ x,
                         const float* __restrict__ wq, const float* __restrict__ bq,
                         const float* __restrict__ wk, const float* __restrict__ bk,
                         const float* __restrict__ wv, const float* __restrict__ bv,
                         const float* __restrict__ w0, const float* __restrict__ w1,
                         const float* __restrict__ w2, const float* __restrict__ w3,
                         const float* __restrict__ mask, const float* __restrict__ pos)
{
    const int blk = blockIdx.x;
    const int tid = threadIdx.x;            // 256 threads

    if (blk >= 8192) {                      // pm = mask + pos
        const int idx4 = ((blk - 8192) * 256 + tid) * 4;
        const int rem = idx4 & 4095;
        float4 mv = *(const float4*)(mask + idx4);
        float4 pv = *(const float4*)(pos + rem);
        float4 o;
        o.x = mv.x + pv.x; o.y = mv.y + pv.y;
        o.z = mv.z + pv.z; o.w = mv.w + pv.w;
        *(float4*)(g_pm + idx4) = o;
        return;
    }
    if (blk >= 4096) {                      // weight rounding
        int idx = (blk - 4096) * 256 + tid;
        int w = idx >> 18, j = idx & 262143;
        const float* s = (w == 0) ? w0 : (w == 1) ? w1 : (w == 2) ? w2 : w3;
        float v = s[j];
        if (w == 0) v *= ATTN_SCALE;
        g_wh[w][j] = __float2half_rn(v);
        return;
    }

    // ---- dw3 (R8 body, byte-identical math) ----
    const int b   = blk >> 2;
    const int c0  = (blk & 3) * 128;

    __shared__ float sx[64][128];
    const float* xb = x + (size_t)b * NTOK * CDIM;

    #pragma unroll
    for (int i = tid; i < 64 * 128; i += 256) {
        int n = i >> 7, c = i & 127;
        sx[n][c] = xb[n * CDIM + c0 + c];
    }
    __syncthreads();

    const int cl   = tid & 127;
    const int c    = c0 + cl;
    const int half = tid >> 7;

    float wqr[9], wkr[9], wvr[9];
    #pragma unroll
    for (int j = 0; j < 9; ++j) {
        wqr[j] = wq[c * 9 + j];
        wkr[j] = wk[c * 9 + j];
        wvr[j] = wv[c * 9 + j];
    }
    const float bqr = bq[c], bkr = bk[c], bvr = bv[c];

    __half* oq = g_scrh[0] + (size_t)b * NTOK * CDIM;
    __half* ok = g_scrh[1] + (size_t)b * NTOK * CDIM;
    __half* ov = g_scrh[2] + (size_t)b * NTOK * CDIM;

    #pragma unroll 4
    for (int nn = 0; nn < 32; ++nn) {
        int n = half * 32 + nn;
        int l = n >> 3, w = n & 7;
        float aq = bqr, ak = bkr, av = bvr;
        #pragma unroll
        for (int dl = -1; dl <= 1; ++dl) {
            #pragma unroll
            for (int dw = -1; dw <= 1; ++dw) {
                int ll = l + dl, ww = w + dw;
                if (ll < 0 || ll > 7 || ww < 0 || ww > 7) continue;
                float xv = sx[ll * 8 + ww][cl];
                int j = (dl + 1) * 3 + (dw + 1);
                aq += xv * wqr[j];
                ak += xv * wkr[j];
                av += xv * wvr[j];
            }
        }
        int idx = n * CDIM + c;
        oq[idx] = __float2half_rn(fmaxf(aq, 0.0f));
        ok[idx] = __float2half_rn(fmaxf(ak, 0.0f));
        ov[idx] = __float2half_rn(fmaxf(av, 0.0f));
    }
}

// ---------------------------------------------------------------------------
// mma.sync / ldmatrix helpers
// ---------------------------------------------------------------------------
__device__ __forceinline__ void mma_f16(float* d, uint32_t a0, uint32_t a1,
                                        uint32_t a2, uint32_t a3,
                                        uint32_t b0, uint32_t b1)
{
    asm volatile(
        "mma.sync.aligned.m16n8k16.row.col.f32.f16.f16.f32 "
        "{%0,%1,%2,%3}, {%4,%5,%6,%7}, {%8,%9}, {%0,%1,%2,%3};"
        : "+f"(d[0]), "+f"(d[1]), "+f"(d[2]), "+f"(d[3])
        : "r"(a0), "r"(a1), "r"(a2), "r"(a3), "r"(b0), "r"(b1));
}

__device__ __forceinline__ void ldsm4(uint32_t& r0, uint32_t& r1,
                                      uint32_t& r2, uint32_t& r3, uint32_t addr)
{
    asm volatile("ldmatrix.sync.aligned.m8n8.x4.shared.b16 {%0,%1,%2,%3}, [%4];"
                 : "=r"(r0), "=r"(r1), "=r"(r2), "=r"(r3) : "r"(addr));
}

__device__ __forceinline__ void ldsm4t(uint32_t& r0, uint32_t& r1,
                                       uint32_t& r2, uint32_t& r3, uint32_t addr)
{
    asm volatile("ldmatrix.sync.aligned.m8n8.x4.trans.shared.b16 {%0,%1,%2,%3}, [%4];"
                 : "=r"(r0), "=r"(r1), "=r"(r2), "=r"(r3) : "r"(addr));
}

__device__ __forceinline__ void cp16(uint32_t dst, const void* src)
{
    asm volatile("cp.async.cg.shared.global [%0], [%1], 16;"
                 :: "r"(dst), "l"(src) : "memory");
}

// ---------------------------------------------------------------------------
// fp16 GEMM body (R8 version, byte-exact — measured best): C = A @ W^T + bias
// CTA 128x128, 128 threads = 4 warps (2x2), warp tile 64x64, m16n8k16.
// K-chunk 16, 3-stage cp.async ring, one sync per chunk.
// Smem rows = 8 half2 data + pad -> pitch 12 half2 (bank-conflict-free).
// ---------------------------------------------------------------------------
#define PADH 12
#define HST  (128 * PADH)                 // half2 (=u32) per stage per matrix

__device__ __forceinline__ void gemm_body_h(const __half* __restrict__ A,
                                            const __half* __restrict__ W,
                                            const float* __restrict__ bias,
                                            float bscale,
                                            __half* __restrict__ Ch,
                                            float* __restrict__ Cf)
{
    __shared__ uint32_t smA[3 * HST];
    __shared__ uint32_t smB[3 * HST];

    const int tid  = threadIdx.x;           // 128 threads
    const int wid  = tid >> 5;
    const int lane = tid & 31;
    const int wm   = wid & 1;
    const int wn   = wid >> 1;
    const int m0 = blockIdx.y * 128;
    const int n0 = blockIdx.x * 128;

    const int lrow = tid >> 1;              // 0..63
    const int seg  = tid & 1;               // 8-half segment within k16

    const int qrow = lane >> 2;
    const int qcol = lane & 3;

    const uint32_t sAb = (uint32_t)__cvta_generic_to_shared(smA);
    const uint32_t sBb = (uint32_t)__cvta_generic_to_shared(smB);

    float acc[4][8][4];
    #pragma unroll
    for (int i = 0; i < 4; ++i)
        #pragma unroll
        for (int j = 0; j < 8; ++j)
            #pragma unroll
            for (int r = 0; r < 4; ++r) acc[i][j][r] = 0.0f;

    const __half* Ap = A + (size_t)(m0 + lrow) * 512 + seg * 8;
    const __half* Bp = W + (size_t)(n0 + lrow) * 512 + seg * 8;

    // prologue: stages 0,1
    #pragma unroll
    for (int st = 0; st < 2; ++st) {
        #pragma unroll
        for (int r = 0; r < 2; ++r) {
            uint32_t off = (uint32_t)(((st * 128 + lrow + r * 64) * PADH + seg * 4) * 4);
            cp16(sAb + off, Ap + (size_t)(r * 64) * 512 + st * 16);
            cp16(sBb + off, Bp + (size_t)(r * 64) * 512 + st * 16);
        }
        asm volatile("cp.async.commit_group;" ::: "memory");
    }

    int s = 0, p = 2;
    #pragma unroll 1
    for (int ch = 0; ch < 32; ++ch) {
        asm volatile("cp.async.wait_group 1;" ::: "memory");
        __syncthreads();

        if (ch < 30) {
            const int kb = (ch + 2) * 16;
            #pragma unroll
            for (int r = 0; r < 2; ++r) {
                uint32_t off = (uint32_t)(((p * 128 + lrow + r * 64) * PADH + seg * 4) * 4);
                cp16(sAb + off, Ap + (size_t)(r * 64) * 512 + kb);
                cp16(sBb + off, Bp + (size_t)(r * 64) * 512 + kb);
            }
        }
        asm volatile("cp.async.commit_group;" ::: "memory");

        const uint32_t* Ab = smA + s * HST;
        const uint32_t* Bb = smB + s * HST;

        uint32_t a[4][4];
        #pragma unroll
        for (int mi = 0; mi < 4; ++mi) {
            const int mr = wm * 64 + mi * 16 + qrow;
            a[mi][0] = Ab[mr * PADH + qcol];
            a[mi][1] = Ab[(mr + 8) * PADH + qcol];
            a[mi][2] = Ab[mr * PADH + qcol + 4];
            a[mi][3] = Ab[(mr + 8) * PADH + qcol + 4];
        }
        uint32_t bfr[8][2];
        #pragma unroll
        for (int ni = 0; ni < 8; ++ni) {
            const int nc = wn * 64 + ni * 8 + qrow;
            bfr[ni][0] = Bb[nc * PADH + qcol];
            bfr[ni][1] = Bb[nc * PADH + qcol + 4];
        }
        #pragma unroll
        for (int mi = 0; mi < 4; ++mi)
            #pragma unroll
            for (int ni = 0; ni < 8; ++ni)
                mma_f16(acc[mi][ni], a[mi][0], a[mi][1], a[mi][2], a[mi][3],
                        bfr[ni][0], bfr[ni][1]);

        s = (s == 2) ? 0 : s + 1;
        p = (p == 2) ? 0 : p + 1;
    }

    // Epilogue: bias (optionally scaled), half2 or float2 stores
    #pragma unroll
    for (int ni = 0; ni < 8; ++ni) {
        const int n = n0 + wn * 64 + ni * 8 + (qcol << 1);
        const float bx = bias[n] * bscale;
        const float by = bias[n + 1] * bscale;
        #pragma unroll
        for (int mi = 0; mi < 4; ++mi) {
            const int m = m0 + wm * 64 + mi * 16 + qrow;
            const float f0 = acc[mi][ni][0] + bx, f1 = acc[mi][ni][1] + by;
            const float f2 = acc[mi][ni][2] + bx, f3 = acc[mi][ni][3] + by;
            if (Ch) {
                *(uint32_t*)(Ch + (size_t)m * 512 + n)       = pack_h2(f0, f1);
                *(uint32_t*)(Ch + (size_t)(m + 8) * 512 + n) = pack_h2(f2, f3);
            } else {
                *(float2*)(Cf + (size_t)m * 512 + n)       = make_float2(f0, f1);
                *(float2*)(Cf + (size_t)(m + 8) * 512 + n) = make_float2(f2, f3);
            }
        }
    }
}

// QKV: grid.z selects slot (0,1,2) -> writes slots (3,4,5).
__global__ void __launch_bounds__(128, 3)
gemm_qkv(const float* __restrict__ bq, const float* __restrict__ bk,
         const float* __restrict__ bv)
{
    const int z = blockIdx.z;
    const float* bias = (z == 0) ? bq : (z == 1) ? bk : bv;
    const float bscale = (z == 0) ? ATTN_SCALE : 1.0f;
    gemm_body_h(g_scrh[z], g_wh[z], bias, bscale, g_scrh[3 + z], nullptr);
}

__global__ void __launch_bounds__(128, 3)
gemm_proj(const float* __restrict__ bias, float* __restrict__ C)
{
    gemm_body_h(g_scrh[0], g_wh[3], bias, 1.0f, nullptr, C);
}

// ---------------------------------------------------------------------------
// Kernel 3: fp16 tensor-core attention (R16 version — measured best).
// One CTA = 8 heads of one window; pm rows in registers across heads.
// ---------------------------------------------------------------------------
__global__ void __launch_bounds__(128)
attn_h()
{
    const int blk = blockIdx.x;            // 2048 blocks
    const int b  = blk >> 1;
    const int h0 = (blk & 1) * 8;          // first head of this CTA's group
    const int tid  = threadIdx.x;
    const int wid  = tid >> 5;
    const int lane = tid & 31;
    const int qrow = lane >> 2;
    const int qcol = lane & 3;
    const int mat  = lane >> 3;
    const int rr   = lane & 7;

    __shared__ uint32_t Qs[64 * 20];   // [token][16 half2 + pad], pitch 80B
    __shared__ uint32_t Ks[64 * 20];
    __shared__ uint32_t Vs[64 * 20];

    const __half* Q = g_scrh[3];
    const __half* K = g_scrh[4];
    const __half* V = g_scrh[5];
    const size_t wbase = (size_t)b * 64 * 512;

    const uint32_t uQ = (uint32_t)__cvta_generic_to_shared(Qs);
    const uint32_t uK = (uint32_t)__cvta_generic_to_shared(Ks);
    const uint32_t uV = (uint32_t)__cvta_generic_to_shared(Vs);

    const int m0 = wid * 16;
    const uint32_t aQ0 = (uint32_t)((m0 + ((mat & 1) << 3) + rr) * 80 + ((mat >> 1) << 4));
    const uint32_t bK0 = (uint32_t)((((mat >> 1) << 3) + rr) * 80 + ((mat & 1) << 4));
    const uint32_t bV0 = (uint32_t)((((mat & 1) << 3) + rr) * 80 + ((mat >> 1) << 4));

    // pos+mask rows for this thread's two C-fragment rows: load ONCE.
    const int r0 = m0 + qrow, r1 = r0 + 8;
    const int cb = qcol * 2;
    float2 pm0[8], pm1[8];
    {
        const float* pmb = g_pm + (size_t)b * 4096;
        #pragma unroll
        for (int nt = 0; nt < 8; ++nt) {
            const int col = nt * 8 + cb;
            pm0[nt] = *(const float2*)(pmb + r0 * 64 + col);
            pm1[nt] = *(const float2*)(pmb + r1 * 64 + col);
        }
    }

    #pragma unroll 1
    for (int hh = 0; hh < 8; ++hh) {
        const size_t base = wbase + (h0 + hh) * 32;

        if (hh > 0) __syncthreads();   // prior head done reading smem
        #pragma unroll
        for (int i = tid; i < 256; i += 128) {
            const int t = i >> 2, g = i & 3;
            const size_t gofs = base + (size_t)t * 512 + g * 8;
            *(uint4*)((char*)Qs + t * 80 + g * 16) = *(const uint4*)(Q + gofs);
            *(uint4*)((char*)Ks + t * 80 + g * 16) = *(const uint4*)(K + gofs);
            *(uint4*)((char*)Vs + t * 80 + g * 16) = *(const uint4*)(V + gofs);
        }
        __syncthreads();

        // S = Q K^T  (warp rows m0..m0+15; q pre-scaled)
        float acc[8][4];
        #pragma unroll
        for (int nt = 0; nt < 8; ++nt)
            #pragma unroll
            for (int r = 0; r < 4; ++r) acc[nt][r] = 0.0f;

        #pragma unroll
        for (int kt = 0; kt < 2; ++kt) {
            uint32_t a0, a1, a2, a3;
            ldsm4(a0, a1, a2, a3, uQ + aQ0 + kt * 32);
            #pragma unroll
            for (int pi = 0; pi < 4; ++pi) {
                uint32_t b0, b1, b2, b3;
                ldsm4(b0, b1, b2, b3, uK + bK0 + pi * 1280 + kt * 32);
                mma_f16(acc[2 * pi],     a0, a1, a2, a3, b0, b1);
                mma_f16(acc[2 * pi + 1], a0, a1, a2, a3, b2, b3);
            }
        }

        // + pm (registers); fragment softmax (quad shfl reductions)
        float mx0 = -1e30f, mx1 = -1e30f;
        #pragma unroll
        for (int nt = 0; nt < 8; ++nt) {
            acc[nt][0] += pm0[nt].x;
            acc[nt][1] += pm0[nt].y;
            acc[nt][2] += pm1[nt].x;
            acc[nt][3] += pm1[nt].y;
            mx0 = fmaxf(mx0, fmaxf(acc[nt][0], acc[nt][1]));
            mx1 = fmaxf(mx1, fmaxf(acc[nt][2], acc[nt][3]));
        }
        mx0 = fmaxf(mx0, __shfl_xor_sync(0xffffffffu, mx0, 1));
        mx0 = fmaxf(mx0, __shfl_xor_sync(0xffffffffu, mx0, 2));
        mx1 = fmaxf(mx1, __shfl_xor_sync(0xffffffffu, mx1, 1));
        mx1 = fmaxf(mx1, __shfl_xor_sync(0xffffffffu, mx1, 2));

        float s0 = 0.0f, s1 = 0.0f;
        #pragma unroll
        for (int nt = 0; nt < 8; ++nt) {
            acc[nt][0] = __expf(acc[nt][0] - mx0);
            acc[nt][1] = __expf(acc[nt][1] - mx0);
            acc[nt][2] = __expf(acc[nt][2] - mx1);
            acc[nt][3] = __expf(acc[nt][3] - mx1);
            s0 += acc[nt][0] + acc[nt][1];
            s1 += acc[nt][2] + acc[nt][3];
        }
        s0 += __shfl_xor_sync(0xffffffffu, s0, 1);
        s0 += __shfl_xor_sync(0xffffffffu, s0, 2);
        s1 += __shfl_xor_sync(0xffffffffu, s1, 1);
        s1 += __shfl_xor_sync(0xffffffffu, s1, 2);
        const float inv0 = 1.0f / s0;
        const float inv1 = 1.0f / s1;

        // O = P V : P a-frags packed directly from the S C-frags (no smem).
        float oacc[4][4];
        #pragma unroll
        for (int nt = 0; nt < 4; ++nt)
            #pragma unroll
            for (int r = 0; r < 4; ++r) oacc[nt][r] = 0.0f;

        #pragma unroll
        for (int kt = 0; kt < 4; ++kt) {
            const uint32_t a0 = pack_h2(acc[2 * kt][0],     acc[2 * kt][1]);
            const uint32_t a1 = pack_h2(acc[2 * kt][2],     acc[2 * kt][3]);
            const uint32_t a2 = pack_h2(acc[2 * kt + 1][0], acc[2 * kt + 1][1]);
            const uint32_t a3 = pack_h2(acc[2 * kt + 1][2], acc[2 * kt + 1][3]);
            #pragma unroll
            for (int np = 0; np < 2; ++np) {
                uint32_t b0, b1, b2, b3;
                ldsm4t(b0, b1, b2, b3, uV + bV0 + kt * 16 * 80 + np * 32);
                mma_f16(oacc[2 * np],     a0, a1, a2, a3, b0, b1);
                mma_f16(oacc[2 * np + 1], a0, a1, a2, a3, b2, b3);
            }
        }

        // normalize, pack, store to slot 0 at [token][h*32+dim]
        __half* O = g_scrh[0] + base;
        #pragma unroll
        for (int nt = 0; nt < 4; ++nt) {
            const int col = nt * 8 + cb;
            *(uint32_t*)(O + (size_t)r0 * 512 + col) =
                pack_h2(oacc[nt][0] * inv0, oacc[nt][1] * inv0);
            *(uint32_t*)(O + (size_t)r1 * 512 + col) =
                pack_h2(oacc[nt][2] * inv1, oacc[nt][3] * inv1);
        }
    }
}

// ---------------------------------------------------------------------------
// Launch
// ---------------------------------------------------------------------------
extern "C" void kernel_launch(void* const* d_in, const int* in_sizes, int n_in,
                              void* d_out, int out_size)
{
    const float* x      = (const float*)d_in[0];
    const float* mask   = (const float*)d_in[1];
    const float* dwq_w  = (const float*)d_in[2];
    const float* dwq_b  = (const float*)d_in[3];
    const float* pwq_w  = (const float*)d_in[4];
    const float* pwq_b  = (const float*)d_in[5];
    const float* dwk_w  = (const float*)d_in[6];
    const float* dwk_b  = (const float*)d_in[7];
    const float* pwk_w  = (const float*)d_in[8];
    const float* pwk_b  = (const float*)d_in[9];
    const float* dwv_w  = (const float*)d_in[10];
    const float* dwv_b  = (const float*)d_in[11];
    const float* pwv_w  = (const float*)d_in[12];
    const float* pwv_b  = (const float*)d_in[13];
    const float* pos    = (const float*)d_in[14];
    const float* proj_w = (const float*)d_in[15];
    const float* proj_b = (const float*)d_in[16];

    // 0+1. merged: dw3 -> slots 0,1,2 ; weight rounding ; pm = mask+pos
    prep_dw3<<<12288, 256>>>(x, dwq_w, dwq_b, dwk_w, dwk_b, dwv_w, dwv_b,
                             pwq_w, pwk_w, pwv_w, proj_w, mask, pos);

    // 2. pointwise GEMMs (fp16 mma) -> slots 3,4,5
    dim3 gqkv(4, 512, 3);
    gemm_qkv<<<gqkv, 128>>>(pwq_b, pwk_b, pwv_b);

    // 3. fp16 tensor-core attention (8 heads per CTA) -> slot 0
    attn_h<<<BW * 2, 128>>>();

    // 4. output projection -> d_out (f32)
    dim3 gg(4, 512);
    gemm_proj<<<gg, 128>>>(proj_b, (float*)d_out);
}